// round 7
// baseline (speedup 1.0000x reference)
#include <cuda_runtime.h>
#include <stdint.h>
#include <math.h>

// ---------------------------------------------------------------------------
// InteractionPredictor e3nn-GNN forward, fp32.
// Fully fused per-edge-tile pipeline: hidden MLP + W-GEMM (smem-only) +
// tensor-product + scatter in ONE kernel. Packed f32x2 FMA throughout.
// ---------------------------------------------------------------------------
#define NMAX  16384
#define EIMAX 40960
#define EIP   40960

__device__ float g_nodeA[NMAX * 40];
__device__ float g_nodeB[NMAX * 40];
__device__ float g_msgs [NMAX * 40];
__device__ __align__(16) float g_tw[320 * 512];          // transposed rec_w1
__device__ __align__(16) float g_Hl[EIMAX * 64];
__device__ __align__(16) float g_Hr[EIMAX * 64];
__device__ __align__(16) float g_Zt[(size_t)320 * EIP];  // transposed Z
__device__ __align__(16) float g_M [(size_t)EIMAX * 512];
__device__ float g_rh[EIMAX * 3];

#define ACT_NORM 1.6789717f
#define PW0_8    0.025515518153991443f   // sqrt(1/24)/8  (== pw1/sqrt3/8)
#define PWREC_8  0.006987712429686843f   // sqrt(1/320)/8
#define INV_SQ3  0.57735026918962576f
#define SQ3F     1.7320508075688772f
#define DEMB_C   37.716086f              // 1.14136 * e^2 * sqrt(20)

__device__ __forceinline__ float silu_act(float s) {
    return s / (1.f + expf(-s)) * ACT_NORM;
}

// ---- packed fp32x2 helpers -------------------------------------------------
__device__ __forceinline__ unsigned long long ffma2(
        unsigned long long a, unsigned long long b, unsigned long long c) {
    unsigned long long d;
    asm("fma.rn.f32x2 %0, %1, %2, %3;" : "=l"(d) : "l"(a), "l"(b), "l"(c));
    return d;
}
__device__ __forceinline__ unsigned long long fpack2(float lo, float hi) {
    unsigned long long d;
    asm("mov.b64 %0, {%1, %2};" : "=l"(d) : "f"(lo), "f"(hi));
    return d;
}
__device__ __forceinline__ float2 funpack2(unsigned long long d) {
    float lo, hi;
    asm("mov.b64 {%0, %1}, %2;" : "=f"(lo), "=f"(hi) : "l"(d));
    return make_float2(lo, hi);
}
__device__ __forceinline__ void cpa16(unsigned int dst, const void* src) {
    asm volatile("cp.async.ca.shared.global [%0], [%1], 16;" :: "r"(dst), "l"(src));
}
__device__ __forceinline__ void cpa_commit() {
    asm volatile("cp.async.commit_group;");
}
__device__ __forceinline__ void cpa_wait0() {
    asm volatile("cp.async.wait_group 0;");
}

// ---------------------------------------------------------------------------
// Tile GEMM: W[64 edges][LEN cols] = As(h^T [64k][64e]) x Bs[64k][LEN].
// 512 threads; item = (eg<8 : 8 edges, q : 4 cols). f32x2 packed along edges.
// ---------------------------------------------------------------------------
template<int LEN>
__device__ __forceinline__ void tile_gemm(const float* As, const float* Bs,
                                          float* Ws, int t) {
    const int NITEMS = 8 * (LEN / 4);
    for (int it = t; it < NITEMS; it += 512) {
        int eg = it & 7, q = it >> 3;
        const float* arow = As + eg * 8;
        const float* brow = Bs + q * 4;
        unsigned long long acc[4][4] = {};
        #pragma unroll 8
        for (int k = 0; k < 64; k++) {
            float4 b4 = *(const float4*)(brow + k * LEN);
            unsigned long long bx = fpack2(b4.x, b4.x);
            unsigned long long by = fpack2(b4.y, b4.y);
            unsigned long long bz = fpack2(b4.z, b4.z);
            unsigned long long bw = fpack2(b4.w, b4.w);
            ulonglong2 a0 = *(const ulonglong2*)(arow + k * 64);
            ulonglong2 a1 = *(const ulonglong2*)(arow + k * 64 + 4);
            unsigned long long av[4] = {a0.x, a0.y, a1.x, a1.y};
            #pragma unroll
            for (int mi = 0; mi < 4; mi++) {
                acc[mi][0] = ffma2(av[mi], bx, acc[mi][0]);
                acc[mi][1] = ffma2(av[mi], by, acc[mi][1]);
                acc[mi][2] = ffma2(av[mi], bz, acc[mi][2]);
                acc[mi][3] = ffma2(av[mi], bw, acc[mi][3]);
            }
        }
        #pragma unroll
        for (int mi = 0; mi < 4; mi++)
            #pragma unroll
            for (int c = 0; c < 4; c++) {
                float2 v = funpack2(acc[mi][c]);
                Ws[(eg * 8 + mi * 2)     * 261 + q * 4 + c] = v.x;
                Ws[(eg * 8 + mi * 2 + 1) * 261 + q * 4 + c] = v.y;
            }
    }
}

template<int LEN>
__device__ __forceinline__ void stage_B(float* Bs, const float* mw1,
                                        int base, int t) {
    const int NQ = LEN / 4;
    for (int idx = t; idx < 64 * NQ; idx += 512) {
        int k = idx / NQ, c4 = (idx - k * NQ) * 4;
        *(float4*)&Bs[k * LEN + c4] =
            *(const float4*)&mw1[k * 576 + base + c4];
    }
}

// Shared TP phase bodies (Fs/Os stride 41, Ws stride 261, Ds stride 8, Rs stride 4)
__device__ __forceinline__ void tp_phase0(const float* Fs, const float* Ws,
                                          float* Os, int t) {
    for (int it = t; it < 1024; it += 512) {
        int e = it & 63, o = it >> 6;
        const float* f = Fs + e * 41;
        const float* w = Ws + e * 261;
        float s = 0.f;
        #pragma unroll
        for (int u = 0; u < 16; u++) s += f[u] * w[u * 16 + o];
        Os[e * 41 + o] += s;
    }
}
__device__ __forceinline__ void tp_phase1(const float* Fs, const float* Ws,
                                          const float* Ds, const float* Rs,
                                          float* Os, int t) {
    for (int it = t; it < 1536; it += 512) {
        if (it < 1024) {
            int e = it & 63, o = it >> 6;
            const float* w = Ws + e * 261;
            float s = 0.f;
            #pragma unroll
            for (int u = 0; u < 8; u++) s += Ds[e * 8 + u] * w[u * 16 + o];
            Os[e * 41 + o] += s;
        } else {
            int j = it - 1024;
            int e = j & 63, wv = j >> 6;
            const float* f = Fs + e * 41;
            const float* w = Ws + e * 261 + 128;
            float cv = 0.f;
            #pragma unroll
            for (int u = 0; u < 16; u++) cv += f[u] * w[u * 8 + wv];
            cv *= SQ3F;
            Os[e * 41 + 16 + wv * 3 + 0] += cv * Rs[e * 4 + 0];
            Os[e * 41 + 16 + wv * 3 + 1] += cv * Rs[e * 4 + 1];
            Os[e * 41 + 16 + wv * 3 + 2] += cv * Rs[e * 4 + 2];
        }
    }
}
__device__ __forceinline__ void tp_phase2(const float* Fs, const float* Ws,
                                          float* Os, int t) {
    if (t < 512) {
        int e = t & 63, wv = t >> 6;
        const float* f = Fs + e * 41 + 16;
        const float* w = Ws + e * 261;
        #pragma unroll
        for (int i = 0; i < 3; i++) {
            float s = 0.f;
            #pragma unroll
            for (int u = 0; u < 8; u++) s += f[u * 3 + i] * w[u * 8 + wv];
            Os[e * 41 + 16 + wv * 3 + i] += s;
        }
    }
}

// ---------------------------------------------------------------------------
// Fused message kernel: 64 edges per block of 512 threads.
// ---------------------------------------------------------------------------
__global__ void __launch_bounds__(512, 1) k_msg_fused(
        const float* __restrict__ pos,
        const int* __restrict__ src, const int* __restrict__ dst,
        const float* __restrict__ eattr,
        const float* __restrict__ mw0,   // [5,64]
        const float* __restrict__ mw1,   // [64,576]
        int E, int use_b) {
    extern __shared__ float sm[];
    float* As  = sm;                    // 4096  : h^T [64k][64e]
    float* Bs  = As + 4096;             // 16384 : mw1 panel [64k][<=256]
    float* Ws  = Bs + 16384;            // 16704 : W tile [64][261]
    float* Fs  = Ws + 16704;            // 2624  : f [64][41]
    float* Os  = Fs + 2624;             // 2624  : out acc [64][41]
    float* Ds  = Os + 2624;             // 512   : dot [64][8]
    float* Rs  = Ds + 512;              // 256   : rhat [64][4]
    float* Eas = Rs + 256;              // 320   : eattr [64][5]
    float* W0s = Eas + 320;             // 320   : mw0
    int* Ssrc = (int*)(W0s + 320);
    int* Sdst = Ssrc + 64;

    const float* node = use_b ? g_nodeB : g_nodeA;
    int t = threadIdx.x;
    int ebase = blockIdx.x * 64;
    int nval = min(64, E - ebase);

    if (t < 64) {
        Ssrc[t] = (t < nval) ? src[ebase + t] : 0;
        Sdst[t] = (t < nval) ? dst[ebase + t] : -1;
    }
    if (t < 320) {
        int e = t / 5;
        Eas[t] = (e < nval) ? eattr[(size_t)ebase * 5 + t] : 0.f;
        W0s[t] = mw0[t];
    }
    for (int idx = t; idx < 2624; idx += 512) Os[idx] = 0.f;
    __syncthreads();

    for (int idx = t; idx < 2560; idx += 512) {
        int e = idx / 40, c = idx - e * 40;
        Fs[e * 41 + c] = (Sdst[e] >= 0) ? node[Ssrc[e] * 40 + c] : 0.f;
    }
    if (t < 64) {
        float rx = 0.f, ry = 0.f, rz = 0.f;
        if (Sdst[t] >= 0) {
            const float* ps = pos + Ssrc[t] * 3;
            const float* pd = pos + Sdst[t] * 3;
            rx = pd[0] - ps[0]; ry = pd[1] - ps[1]; rz = pd[2] - ps[2];
            float inv = rsqrtf(rx * rx + ry * ry + rz * rz);
            rx *= inv; ry *= inv; rz *= inv;
        }
        Rs[t * 4 + 0] = rx; Rs[t * 4 + 1] = ry; Rs[t * 4 + 2] = rz;
    }
    {   // hidden: thread -> (e = t>>3, kb = (t&7)*8)
        int e = t >> 3, kb = (t & 7) * 8;
        float ea[5];
        #pragma unroll
        for (int a = 0; a < 5; a++) ea[a] = Eas[e * 5 + a];
        #pragma unroll
        for (int j = 0; j < 8; j++) {
            int k = kb + j;
            float s = 0.f;
            #pragma unroll
            for (int a = 0; a < 5; a++) s += ea[a] * W0s[a * 64 + k];
            As[k * 64 + e] = silu_act(s * 0.4472135954999579f);   // 1/sqrt(5)
        }
    }
    __syncthreads();
    {   // dot: (e = t>>3, u = t&7)
        int e = t >> 3, u = t & 7;
        Ds[e * 8 + u] = Fs[e * 41 + 16 + u * 3]     * Rs[e * 4]
                      + Fs[e * 41 + 17 + u * 3]     * Rs[e * 4 + 1]
                      + Fs[e * 41 + 18 + u * 3]     * Rs[e * 4 + 2];
    }
    __syncthreads();

    // phase 0: A block (cols 0..255)
    stage_B<256>(Bs, mw1, 0, t);
    __syncthreads();
    tile_gemm<256>(As, Bs, Ws, t);
    __syncthreads();
    tp_phase0(Fs, Ws, Os, t);
    __syncthreads();

    // phase 1: B+C blocks (cols 256..511)
    stage_B<256>(Bs, mw1, 256, t);
    __syncthreads();
    tile_gemm<256>(As, Bs, Ws, t);
    __syncthreads();
    tp_phase1(Fs, Ws, Ds, Rs, Os, t);
    __syncthreads();

    // phase 2: D block (cols 512..575)
    stage_B<64>(Bs, mw1, 512, t);
    __syncthreads();
    tile_gemm<64>(As, Bs, Ws, t);
    __syncthreads();
    tp_phase2(Fs, Ws, Os, t);
    __syncthreads();

    for (int it = t; it < 2560; it += 512) {
        int e = it / 40, o = it - e * 40;
        int d = Sdst[e];
        if (d >= 0) atomicAdd(&g_msgs[d * 40 + o], PW0_8 * Os[e * 41 + o]);
    }
}

// ---------------------------------------------------------------------------
// Fused lig kernel: 64 inter-edges/block; hidden from g_Hl; writes Zt.
// ---------------------------------------------------------------------------
__global__ void __launch_bounds__(512, 1) k_lig_fused(
        const int* __restrict__ irec, const int* __restrict__ ilig,
        const float* __restrict__ lw1,   // [64,576]
        int EI) {
    extern __shared__ float sm[];
    float* As  = sm;                    // 4096
    float* Bs  = As + 4096;             // 16384
    float* Ws  = Bs + 16384;            // 16704
    float* Fl  = Ws + 16704;            // 2624
    float* Fr  = Fl + 2624;             // 2624
    float* Os  = Fr + 2624;             // 2624
    float* Ds  = Os + 2624;             // 512
    float* Rs  = Ds + 512;              // 256
    int* Sil = (int*)(Rs + 256);
    int* Sir = Sil + 64;

    int t = threadIdx.x;
    int ebase = blockIdx.x * 64;
    int nval = min(64, EI - ebase);

    if (t < 64) {
        Sir[t] = (t < nval) ? irec[ebase + t] : 0;
        Sil[t] = (t < nval) ? ilig[ebase + t] : 0;
    }
    for (int idx = t; idx < 2624; idx += 512) Os[idx] = 0.f;
    __syncthreads();

    for (int idx = t; idx < 2560; idx += 512) {
        int e = idx / 40, c = idx - e * 40;
        float vl = 0.f, vr = 0.f;
        if (e < nval) {
            vl = g_nodeA[Sil[e] * 40 + c];
            vr = g_nodeA[Sir[e] * 40 + c];
        }
        Fl[e * 41 + c] = vl;
        Fr[e * 41 + c] = vr;
    }
    if (t < 64) {
        float rx = 0.f, ry = 0.f, rz = 0.f;
        if (t < nval) {
            rx = g_rh[(ebase + t) * 3];
            ry = g_rh[(ebase + t) * 3 + 1];
            rz = g_rh[(ebase + t) * 3 + 2];
        }
        Rs[t * 4 + 0] = rx; Rs[t * 4 + 1] = ry; Rs[t * 4 + 2] = rz;
    }
    for (int idx = t; idx < 1024; idx += 512) {   // As from g_Hl (transpose)
        int e = idx >> 4, k4 = (idx & 15) * 4;
        float4 v = make_float4(0.f, 0.f, 0.f, 0.f);
        if (e < nval) v = *(const float4*)&g_Hl[(size_t)(ebase + e) * 64 + k4];
        As[(k4 + 0) * 64 + e] = v.x;
        As[(k4 + 1) * 64 + e] = v.y;
        As[(k4 + 2) * 64 + e] = v.z;
        As[(k4 + 3) * 64 + e] = v.w;
    }
    __syncthreads();
    {
        int e = t >> 3, u = t & 7;
        Ds[e * 8 + u] = Fl[e * 41 + 16 + u * 3]     * Rs[e * 4]
                      + Fl[e * 41 + 17 + u * 3]     * Rs[e * 4 + 1]
                      + Fl[e * 41 + 18 + u * 3]     * Rs[e * 4 + 2];
    }
    __syncthreads();

    stage_B<256>(Bs, lw1, 0, t);
    __syncthreads();
    tile_gemm<256>(As, Bs, Ws, t);
    __syncthreads();
    tp_phase0(Fl, Ws, Os, t);
    __syncthreads();

    stage_B<256>(Bs, lw1, 256, t);
    __syncthreads();
    tile_gemm<256>(As, Bs, Ws, t);
    __syncthreads();
    tp_phase1(Fl, Ws, Ds, Rs, Os, t);
    __syncthreads();

    stage_B<64>(Bs, lw1, 512, t);
    __syncthreads();
    tile_gemm<64>(As, Bs, Ws, t);
    __syncthreads();
    tp_phase2(Fl, Ws, Os, t);
    __syncthreads();

    for (int it = t; it < 2560; it += 512) {   // finalize lig_emb scale
        int e = it / 40, o = it - e * 40;
        Os[e * 41 + o] *= PW0_8;
    }
    __syncthreads();

    for (int it = t; it < 64 * 320; it += 512) {   // Z (transposed write)
        int p = it >> 6, e = it & 63;
        if (e >= nval) continue;
        float z;
        if (p < 256) {
            z = Os[e * 41 + (p >> 4)] * Fr[e * 41 + (p & 15)];
        } else {
            int q = p - 256; int u = q >> 3, v = q & 7;
            z = (Os[e * 41 + 16 + u * 3]     * Fr[e * 41 + 16 + v * 3]
               + Os[e * 41 + 17 + u * 3]     * Fr[e * 41 + 17 + v * 3]
               + Os[e * 41 + 18 + u * 3]     * Fr[e * 41 + 18 + v * 3]) * INV_SQ3;
        }
        g_Zt[(size_t)p * EIP + ebase + e] = z;
    }
}

// ---------------------------------------------------------------------------
// Transpose rec_w1 [64,2560] -> TW[320,512]
// ---------------------------------------------------------------------------
__global__ void k_transpose(const float* __restrict__ rw1) {
    int idx = blockIdx.x * 256 + threadIdx.x;
    if (idx >= 320 * 512) return;
    int p = idx >> 9, r = idx & 511;
    int k = r >> 3, w = r & 7;
    g_tw[idx] = rw1[k * 2560 + p * 8 + w];
}

// ---------------------------------------------------------------------------
// Node embedding MLP + zero geo + zero msgs.
// ---------------------------------------------------------------------------
__global__ void k_embed(const float* __restrict__ x,
                        const float* __restrict__ w0,   // [10,64]
                        const float* __restrict__ w1,   // [64,16]
                        int N) {
    __shared__ float sh[8][64];
    int warp = threadIdx.x >> 5, lane = threadIdx.x & 31;
    int n = blockIdx.x * 8 + warp;
    if (n >= N) return;
    float xa[10];
    #pragma unroll
    for (int a = 0; a < 10; a++) xa[a] = x[n * 10 + a];
    #pragma unroll
    for (int r = 0; r < 2; r++) {
        int k = lane + r * 32;
        float s = 0.f;
        #pragma unroll
        for (int a = 0; a < 10; a++) s += xa[a] * w0[a * 64 + k];
        sh[warp][k] = silu_act(s * 0.31622776601683794f);   // 1/sqrt(10)
    }
    __syncwarp();
    if (lane < 16) {
        float s = 0.f;
        #pragma unroll
        for (int k = 0; k < 64; k++) s += sh[warp][k] * w1[k * 16 + lane];
        g_nodeA[n * 40 + lane] = s * 0.125f;                // 1/sqrt(64)
    }
    if (lane < 24) g_nodeA[n * 40 + 16 + lane] = 0.f;
    g_msgs[n * 40 + lane] = 0.f;
    if (lane < 8) g_msgs[n * 40 + 32 + lane] = 0.f;
}

// ---------------------------------------------------------------------------
// Update step. Re-zeroes g_msgs.
// ---------------------------------------------------------------------------
__global__ void k_upd(const float* __restrict__ uw0,   // [32,64]
                      const float* __restrict__ uw1,   // [64,16]
                      const float* __restrict__ imp,
                      int N, float degInv, int step) {
    __shared__ float cat[8][32];
    __shared__ float hh[8][64];
    int warp = threadIdx.x >> 5, lane = threadIdx.x & 31;
    int n = blockIdx.x * 8 + warp;
    if (n >= N) return;
    const float* in = step ? g_nodeB : g_nodeA;
    float* out = step ? g_nodeA : g_nodeB;
    float sc = imp[0] * degInv;
    float gscale = step ? 0.5f : 1.0f;
    if (lane < 16) {
        cat[warp][lane]      = g_msgs[n * 40 + lane] * sc;
        cat[warp][16 + lane] = in[n * 40 + lane];
    }
    __syncwarp();
    #pragma unroll
    for (int r = 0; r < 2; r++) {
        int k = lane + r * 32;
        float s = 0.f;
        #pragma unroll
        for (int a = 0; a < 32; a++) s += cat[warp][a] * uw0[a * 64 + k];
        hh[warp][k] = silu_act(s * 0.17677669529663687f);   // 1/sqrt(32)
    }
    __syncwarp();
    if (lane < 16) {
        float s = 0.f;
        #pragma unroll
        for (int k = 0; k < 64; k++) s += hh[warp][k] * uw1[k * 16 + lane];
        out[n * 40 + lane] = s * 0.125f;
    }
    if (lane < 24)
        out[n * 40 + 16 + lane] =
            (g_msgs[n * 40 + 16 + lane] * sc + in[n * 40 + 16 + lane]) * gscale;
    g_msgs[n * 40 + lane] = 0.f;
    if (lane < 8) g_msgs[n * 40 + 32 + lane] = 0.f;
}

// ---------------------------------------------------------------------------
// Inter-edge prep: rhat + dist-embed -> Hl, Hr.
// ---------------------------------------------------------------------------
__global__ void k_prep(const float* __restrict__ pos,
                       const int* __restrict__ irec, const int* __restrict__ ilig,
                       const float* __restrict__ lw0,   // [20,64]
                       const float* __restrict__ rw0,   // [20,64]
                       int EI) {
    int idx = blockIdx.x * 256 + threadIdx.x;
    int e = idx >> 6, k = idx & 63;
    if (e >= EI) return;
    int ir = irec[e], il = ilig[e];
    float rx = pos[il * 3]     - pos[ir * 3];
    float ry = pos[il * 3 + 1] - pos[ir * 3 + 1];
    float rz = pos[il * 3 + 2] - pos[ir * 3 + 2];
    float d = sqrtf(rx * rx + ry * ry + rz * rz);
    float inv = 1.f / d;
    if (k == 0) {
        g_rh[e * 3]     = rx * inv;
        g_rh[e * 3 + 1] = ry * inv;
        g_rh[e * 3 + 2] = rz * inv;
    }
    float s1 = 0.f, s2 = 0.f;
    #pragma unroll
    for (int a = 0; a < 20; a++) {
        float diff = d * (21.f / 5.f) - (float)(a + 1);
        float t1 = diff + 1.f, t2 = 1.f - diff;
        float v = 0.f;
        if (t1 > 0.f && t2 > 0.f) v = DEMB_C * expf(-1.f / t1 - 1.f / t2);
        s1 += v * lw0[a * 64 + k];
        s2 += v * rw0[a * 64 + k];
    }
    g_Hl[idx] = silu_act(s1 * 0.22360679774997896f);   // 1/sqrt(20)
    g_Hr[idx] = silu_act(s2 * 0.22360679774997896f);
}

// ---------------------------------------------------------------------------
// Rec GEMM: M[EI,512] = Z @ TW. A = Zt (K-major [320][EIP]), f32x2.
// ---------------------------------------------------------------------------
__global__ void __launch_bounds__(256) k_gemm_rec(
        const float* __restrict__ Zt, const float* __restrict__ TW,
        float* __restrict__ C, int M) {
    extern __shared__ float sm[];
    float* As = sm;            // [2][32][128]
    float* Bs = As + 8192;     // [2][32][64]
    unsigned int sAs = (unsigned int)__cvta_generic_to_shared(As);
    unsigned int sBs = (unsigned int)__cvta_generic_to_shared(Bs);
    int t = threadIdx.x;
    int rowBase = blockIdx.y * 128;
    int nBase   = blockIdx.x * 64;
    int tx = t & 15, ty = t >> 4;

    {
        #pragma unroll
        for (int i = 0; i < 4; i++) {
            int c = t + i * 256;
            int kr = c >> 5, c4 = (c & 31) * 4;
            cpa16(sAs + (kr * 128 + c4) * 4, Zt + (size_t)kr * EIP + rowBase + c4);
        }
        #pragma unroll
        for (int i = 0; i < 2; i++) {
            int c = t + i * 256;
            int kr = c >> 4, c4 = (c & 15) * 4;
            cpa16(sBs + (kr * 64 + c4) * 4, TW + kr * 512 + nBase + c4);
        }
        cpa_commit();
    }

    unsigned long long acc[4][4] = {};
    for (int it = 0; it < 10; it++) {
        cpa_wait0();
        __syncthreads();
        if (it + 1 < 10) {
            int k0 = (it + 1) * 32;
            int b = (it + 1) & 1;
            #pragma unroll
            for (int i = 0; i < 4; i++) {
                int c = t + i * 256;
                int kr = c >> 5, c4 = (c & 31) * 4;
                cpa16(sAs + (b * 4096 + kr * 128 + c4) * 4,
                      Zt + (size_t)(k0 + kr) * EIP + rowBase + c4);
            }
            #pragma unroll
            for (int i = 0; i < 2; i++) {
                int c = t + i * 256;
                int kr = c >> 4, c4 = (c & 15) * 4;
                cpa16(sBs + (b * 2048 + kr * 64 + c4) * 4,
                      TW + (k0 + kr) * 512 + nBase + c4);
            }
            cpa_commit();
        }
        const float* Ab = As + (it & 1) * 4096;
        const float* Bb = Bs + (it & 1) * 2048;
        #pragma unroll 8
        for (int k = 0; k < 32; k++) {
            float4 b4 = *(const float4*)&Bb[k * 64 + tx * 4];
            unsigned long long bx = fpack2(b4.x, b4.x);
            unsigned long long by = fpack2(b4.y, b4.y);
            unsigned long long bz = fpack2(b4.z, b4.z);
            unsigned long long bw = fpack2(b4.w, b4.w);
            ulonglong2 a0 = *(const ulonglong2*)&Ab[k * 128 + ty * 8];
            ulonglong2 a1 = *(const ulonglong2*)&Ab[k * 128 + ty * 8 + 4];
            unsigned long long av[4] = {a0.x, a0.y, a1.x, a1.y};
            #pragma unroll
            for (int mi = 0; mi < 4; mi++) {
                acc[mi][0] = ffma2(av[mi], bx, acc[mi][0]);
                acc[mi][1] = ffma2(av[mi], by, acc[mi][1]);
                acc[mi][2] = ffma2(av[mi], bz, acc[mi][2]);
                acc[mi][3] = ffma2(av[mi], bw, acc[mi][3]);
            }
        }
        __syncthreads();
    }
    #pragma unroll
    for (int mi = 0; mi < 4; mi++) {
        float2 c0 = funpack2(acc[mi][0]);
        float2 c1 = funpack2(acc[mi][1]);
        float2 c2 = funpack2(acc[mi][2]);
        float2 c3 = funpack2(acc[mi][3]);
        int r0 = rowBase + ty * 8 + mi * 2;
        if (r0 < M)
            *(float4*)(C + (size_t)r0 * 512 + nBase + tx * 4) =
                make_float4(c0.x, c1.x, c2.x, c3.x);
        if (r0 + 1 < M)
            *(float4*)(C + (size_t)(r0 + 1) * 512 + nBase + tx * 4) =
                make_float4(c0.y, c1.y, c2.y, c3.y);
    }
}

// ---------------------------------------------------------------------------
// Output: out[e,w] = PWREC_8 * sum_k Hr[e,k] * M[e,k*8+w]
// ---------------------------------------------------------------------------
__global__ void k_out(float* __restrict__ outp, int EI) {
    int idx = blockIdx.x * 256 + threadIdx.x;
    int e = idx >> 3, w = idx & 7;
    if (e >= EI) return;
    float s = 0.f;
    #pragma unroll
    for (int k = 0; k < 64; k++)
        s += g_Hr[e * 64 + k] * g_M[(size_t)e * 512 + k * 8 + w];
    outp[idx] = PWREC_8 * s;
}

// ---------------------------------------------------------------------------
extern "C" void kernel_launch(void* const* d_in, const int* in_sizes, int n_in,
                              void* d_out, int out_size) {
    const float* x     = (const float*)d_in[0];
    const float* pos   = (const float*)d_in[1];
    const int*   eidx  = (const int*)  d_in[2];
    const float* eattr = (const float*)d_in[3];
    const int*   iidx  = (const int*)  d_in[4];
    const float* emb_w0= (const float*)d_in[5];
    const float* emb_w1= (const float*)d_in[6];
    const float* imp0  = (const float*)d_in[7];
    const float* m0w0  = (const float*)d_in[8];
    const float* m0w1  = (const float*)d_in[9];
    const float* u0w0  = (const float*)d_in[10];
    const float* u0w1  = (const float*)d_in[11];
    const float* imp1  = (const float*)d_in[12];
    const float* m1w0  = (const float*)d_in[13];
    const float* m1w1  = (const float*)d_in[14];
    const float* u1w0  = (const float*)d_in[15];
    const float* u1w1  = (const float*)d_in[16];
    const float* lw0   = (const float*)d_in[17];
    const float* lw1   = (const float*)d_in[18];
    const float* rw0   = (const float*)d_in[19];
    const float* rw1   = (const float*)d_in[20];
    float* outp = (float*)d_out;

    int N  = in_sizes[0] / 10;
    int E  = in_sizes[2] / 2;
    int EI = in_sizes[4] / 2;
    float degInv = (float)(1.0 / sqrt((double)E / (double)N));

    float *pZt, *pM, *pTW;
    cudaGetSymbolAddress((void**)&pZt, g_Zt);
    cudaGetSymbolAddress((void**)&pM,  g_M);
    cudaGetSymbolAddress((void**)&pTW, g_tw);

    const int SM_MSG = (4096 + 16384 + 16704 + 2624 + 2624 + 512 + 256
                        + 320 + 320) * 4 + 128 * 4;          // 175872
    const int SM_LIG = (4096 + 16384 + 16704 + 2624 + 2624 + 2624 + 512
                        + 256) * 4 + 128 * 4;                // 183808
    const int SM_REC = (8192 + 4096) * 4;                    // 49152
    cudaFuncSetAttribute(k_msg_fused, cudaFuncAttributeMaxDynamicSharedMemorySize, SM_MSG);
    cudaFuncSetAttribute(k_lig_fused, cudaFuncAttributeMaxDynamicSharedMemorySize, SM_LIG);
    cudaFuncSetAttribute(k_gemm_rec,  cudaFuncAttributeMaxDynamicSharedMemorySize, SM_REC);

    k_transpose<<<(320 * 512 + 255) / 256, 256>>>(rw1);
    k_embed<<<(N + 7) / 8, 256>>>(x, emb_w0, emb_w1, N);

    int gE = (E + 63) / 64;
    k_msg_fused<<<gE, 512, SM_MSG>>>(pos, eidx, eidx + E, eattr, m0w0, m0w1, E, 0);
    k_upd<<<(N + 7) / 8, 256>>>(u0w0, u0w1, imp0, N, degInv, 0);
    k_msg_fused<<<gE, 512, SM_MSG>>>(pos, eidx, eidx + E, eattr, m1w0, m1w1, E, 1);
    k_upd<<<(N + 7) / 8, 256>>>(u1w0, u1w1, imp1, N, degInv, 1);

    k_prep<<<(EI * 64 + 255) / 256, 256>>>(pos, iidx, iidx + EI, lw0, rw0, EI);
    int gI = (EI + 63) / 64;
    k_lig_fused<<<gI, 512, SM_LIG>>>(iidx, iidx + EI, lw1, EI);
    dim3 gM(8, (EI + 127) / 128);
    k_gemm_rec<<<gM, 256, SM_REC>>>(pZt, pTW, pM, EI);
    k_out<<<(EI * 8 + 255) / 256, 256>>>(outp, EI);
}

// round 9
// speedup vs baseline: 1.2712x; 1.2712x over previous
#include <cuda_runtime.h>
#include <cuda_bf16.h>
#include <stdint.h>
#include <math.h>

// ---------------------------------------------------------------------------
// InteractionPredictor e3nn-GNN forward.
// Message passes: warp-level mma.sync m16n8k16 bf16 (hi/lo split, fp32 acc)
// fused with tensor-product epilogue in registers + atomic scatter.
// Lig/rec path: validated fp32 GEMM kernels.
// ---------------------------------------------------------------------------
#define NMAX  16384
#define EIMAX 40960
#define EIP   40960

__device__ __align__(16) float g_nodeA[NMAX * 40];
__device__ __align__(16) float g_nodeB[NMAX * 40];
__device__ __align__(16) float g_msgs [NMAX * 40];
__device__ __align__(16) float g_tw[320 * 512];           // transposed rec_w1
__device__ __align__(16) float g_Wl[(size_t)EIMAX * 576]; // lig TP weights
__device__ __align__(16) float g_Hl[EIMAX * 64];
__device__ __align__(16) float g_Hr[EIMAX * 64];
__device__ __align__(16) float g_Zt[(size_t)320 * EIP];   // transposed Z
__device__ __align__(16) float g_M [(size_t)EIMAX * 512];
__device__ float g_rh[EIMAX * 3];
// pre-transposed bf16 hi/lo images: Bt[j*64+k] = mw1[k][j]
__device__ __align__(16) __nv_bfloat16 g_Bth[2][576 * 64];
__device__ __align__(16) __nv_bfloat16 g_Btl[2][576 * 64];

#define ACT_NORM 1.6789717f
#define PW0_8    0.025515518153991443f   // sqrt(1/24)/8
#define PW1_8    0.044194173824159216f   // sqrt(1/8)/8
#define PWREC_8  0.006987712429686843f   // sqrt(1/320)/8
#define INV_SQ3  0.57735026918962576f
#define SQ3F     1.7320508075688772f
#define DEMB_C   37.716086f

__device__ __forceinline__ float silu_act(float s) {
    return s / (1.f + expf(-s)) * ACT_NORM;
}
__device__ __forceinline__ void cpa16(unsigned int dst, const void* src) {
    asm volatile("cp.async.ca.shared.global [%0], [%1], 16;" :: "r"(dst), "l"(src));
}
__device__ __forceinline__ void cpa_commit() { asm volatile("cp.async.commit_group;"); }
__device__ __forceinline__ void cpa_wait0()  { asm volatile("cp.async.wait_group 0;"); }

__device__ __forceinline__ void mma16816(float d[4],
        unsigned a0, unsigned a1, unsigned a2, unsigned a3,
        unsigned b0, unsigned b1) {
    asm volatile(
        "mma.sync.aligned.m16n8k16.row.col.f32.bf16.bf16.f32 "
        "{%0,%1,%2,%3}, {%4,%5,%6,%7}, {%8,%9}, {%0,%1,%2,%3};"
        : "+f"(d[0]), "+f"(d[1]), "+f"(d[2]), "+f"(d[3])
        : "r"(a0), "r"(a1), "r"(a2), "r"(a3), "r"(b0), "r"(b1));
}

// ---------------------------------------------------------------------------
// Pre-transpose+split mw1 -> Bt images: Bt[j*64+k] = mw1[k][j] (bf16 hi/lo)
// ---------------------------------------------------------------------------
__global__ void k_prepB(const float* __restrict__ mw1, int which) {
    int idx = blockIdx.x * 256 + threadIdx.x;
    if (idx >= 576 * 64) return;
    int j = idx >> 6, k = idx & 63;
    float v = mw1[k * 576 + j];
    __nv_bfloat16 hi = __float2bfloat16(v);
    __nv_bfloat16 lo = __float2bfloat16(v - __bfloat162float(hi));
    g_Bth[which][idx] = hi;
    g_Btl[which][idx] = lo;
}

// ---------------------------------------------------------------------------
// TP register-accumulation for one 8-col tile of W fragments.
// d[4]: (edge r0, col c0), (r0, c0+1), (r0+8, c0), (r0+8, c0+1)
// ---------------------------------------------------------------------------
__device__ __forceinline__ void tp_acc(int jb, const float d[4],
        float accS[2][4], float accG[2][2][3],
        const float* Fs, const float* Ds, const float rh[2][3], int le0) {
    int le1 = le0 + 8;
    if (jb < 256) {
        int u = jb >> 4, oh = (jb >> 3) & 1;
        float f0 = Fs[le0 * 41 + u];
        float f1 = Fs[le1 * 41 + u];
        accS[0][oh * 2 + 0] += f0 * d[0];
        accS[0][oh * 2 + 1] += f0 * d[1];
        accS[1][oh * 2 + 0] += f1 * d[2];
        accS[1][oh * 2 + 1] += f1 * d[3];
    } else if (jb < 384) {
        int u = (jb - 256) >> 4, oh = (jb >> 3) & 1;
        float f0 = Ds[le0 * 8 + u];
        float f1 = Ds[le1 * 8 + u];
        accS[0][oh * 2 + 0] += f0 * d[0];
        accS[0][oh * 2 + 1] += f0 * d[1];
        accS[1][oh * 2 + 0] += f1 * d[2];
        accS[1][oh * 2 + 1] += f1 * d[3];
    } else if (jb < 512) {
        int u = (jb - 384) >> 3;
        float f0 = SQ3F * Fs[le0 * 41 + u];
        float f1 = SQ3F * Fs[le1 * 41 + u];
        #pragma unroll
        for (int i = 0; i < 3; i++) {
            accG[0][0][i] += f0 * d[0] * rh[0][i];
            accG[0][1][i] += f0 * d[1] * rh[0][i];
            accG[1][0][i] += f1 * d[2] * rh[1][i];
            accG[1][1][i] += f1 * d[3] * rh[1][i];
        }
    } else {
        int u = (jb - 512) >> 3;
        #pragma unroll
        for (int i = 0; i < 3; i++) {
            float f0 = Fs[le0 * 41 + 16 + u * 3 + i];
            float f1 = Fs[le1 * 41 + 16 + u * 3 + i];
            accG[0][0][i] += f0 * d[0];
            accG[0][1][i] += f0 * d[1];
            accG[1][0][i] += f1 * d[2];
            accG[1][1][i] += f1 * d[3];
        }
    }
}

// ---------------------------------------------------------------------------
// Fused msg pass: 64 edges / block, 128 threads (4 warps x 16 edges).
// ---------------------------------------------------------------------------
__global__ void __launch_bounds__(128) k_msg_mma(
        const float* __restrict__ pos,
        const int* __restrict__ src, const int* __restrict__ dst,
        const float* __restrict__ eattr,
        const float* __restrict__ mw0,              // [5,64]
        const __nv_bfloat16* __restrict__ Bth,      // [576*64]
        const __nv_bfloat16* __restrict__ Btl,
        int E, int use_b) {
    __shared__ __nv_bfloat16 Hh[64 * 66];
    __shared__ __nv_bfloat16 Hl[64 * 66];
    __shared__ float Fs[64 * 41];
    __shared__ float Ds[64 * 8];
    __shared__ float Rs[64 * 4];
    __shared__ int   Ssrc[64];
    __shared__ int   Sdst[64];

    const float* node = use_b ? g_nodeB : g_nodeA;
    int t = threadIdx.x;
    int warp = t >> 5, lane = t & 31;
    int ebase = blockIdx.x * 64;

    if (t < 64) {
        int eid = ebase + t;
        Ssrc[t] = (eid < E) ? src[eid] : 0;
        Sdst[t] = (eid < E) ? dst[eid] : -1;
    }
    __syncthreads();

    // hidden layer -> bf16 hi/lo A panels (thread: edge t>>1, k-half (t&1)*32)
    {
        int eh = t >> 1, kb = (t & 1) * 32;
        bool hv = (ebase + eh) < E;
        float ea[5];
        #pragma unroll
        for (int a = 0; a < 5; a++)
            ea[a] = hv ? eattr[(size_t)(ebase + eh) * 5 + a] : 0.f;
        #pragma unroll
        for (int kk = 0; kk < 32; kk += 2) {
            int k = kb + kk;
            float s0 = 0.f, s1 = 0.f;
            #pragma unroll
            for (int a = 0; a < 5; a++) {
                s0 += ea[a] * __ldg(&mw0[a * 64 + k]);
                s1 += ea[a] * __ldg(&mw0[a * 64 + k + 1]);
            }
            float h0 = silu_act(s0 * 0.4472135954999579f);
            float h1 = silu_act(s1 * 0.4472135954999579f);
            __nv_bfloat16 h0h = __float2bfloat16(h0);
            __nv_bfloat16 h1h = __float2bfloat16(h1);
            __nv_bfloat16 h0l = __float2bfloat16(h0 - __bfloat162float(h0h));
            __nv_bfloat16 h1l = __float2bfloat16(h1 - __bfloat162float(h1h));
            *(__nv_bfloat162*)&Hh[eh * 66 + k] = __nv_bfloat162(h0h, h1h);
            *(__nv_bfloat162*)&Hl[eh * 66 + k] = __nv_bfloat162(h0l, h1l);
        }
    }
    // gather node features
    for (int idx = t; idx < 2560; idx += 128) {
        int e = idx / 40, c = idx - e * 40;
        Fs[e * 41 + c] = (Sdst[e] >= 0) ? node[(size_t)Ssrc[e] * 40 + c] : 0.f;
    }
    if (t < 64) {
        float rx = 0.f, ry = 0.f, rz = 0.f;
        if (Sdst[t] >= 0) {
            const float* ps = pos + Ssrc[t] * 3;
            const float* pd = pos + Sdst[t] * 3;
            rx = pd[0] - ps[0]; ry = pd[1] - ps[1]; rz = pd[2] - ps[2];
            float inv = rsqrtf(rx * rx + ry * ry + rz * rz);
            rx *= inv; ry *= inv; rz *= inv;
        }
        Rs[t * 4] = rx; Rs[t * 4 + 1] = ry; Rs[t * 4 + 2] = rz;
    }
    __syncthreads();

    // dot products xv . rhat
    for (int idx = t; idx < 512; idx += 128) {
        int e = idx >> 3, u = idx & 7;
        Ds[idx] = Fs[e * 41 + 16 + u * 3]     * Rs[e * 4]
                + Fs[e * 41 + 17 + u * 3]     * Rs[e * 4 + 1]
                + Fs[e * 41 + 18 + u * 3]     * Rs[e * 4 + 2];
    }
    __syncthreads();

    // A fragments (all 4 k-steps, hi and lo) held in registers
    int r0 = lane >> 2;                 // 0..7
    int c0 = (lane & 3) * 2;            // 0,2,4,6
    int le0 = warp * 16 + r0;
    int le1 = le0 + 8;
    unsigned ah[4][4], al[4][4];
    #pragma unroll
    for (int ks = 0; ks < 4; ks++) {
        int kb = ks * 16 + c0;
        ah[ks][0] = *(const unsigned*)&Hh[le0 * 66 + kb];
        ah[ks][1] = *(const unsigned*)&Hh[le1 * 66 + kb];
        ah[ks][2] = *(const unsigned*)&Hh[le0 * 66 + kb + 8];
        ah[ks][3] = *(const unsigned*)&Hh[le1 * 66 + kb + 8];
        al[ks][0] = *(const unsigned*)&Hl[le0 * 66 + kb];
        al[ks][1] = *(const unsigned*)&Hl[le1 * 66 + kb];
        al[ks][2] = *(const unsigned*)&Hl[le0 * 66 + kb + 8];
        al[ks][3] = *(const unsigned*)&Hl[le1 * 66 + kb + 8];
    }
    float rh[2][3];
    #pragma unroll
    for (int i = 0; i < 3; i++) {
        rh[0][i] = Rs[le0 * 4 + i];
        rh[1][i] = Rs[le1 * 4 + i];
    }

    float accS[2][4] = {};
    float accG[2][2][3] = {};
    int n = lane >> 2;                   // b-frag column within tile (== r0)
    int kc = c0;                         // b-frag k offset

    #pragma unroll 1
    for (int tp = 0; tp < 36; tp++) {
        int jb0 = tp * 16, jb1 = jb0 + 8;
        const __nv_bfloat16* bh0p = Bth + (size_t)(jb0 + n) * 64 + kc;
        const __nv_bfloat16* bl0p = Btl + (size_t)(jb0 + n) * 64 + kc;
        float dA[4] = {}, dB[4] = {};
        #pragma unroll
        for (int ks = 0; ks < 4; ks++) {
            unsigned bh0 = *(const unsigned*)(bh0p + ks * 16);
            unsigned bh1 = *(const unsigned*)(bh0p + ks * 16 + 8);
            unsigned bl0 = *(const unsigned*)(bl0p + ks * 16);
            unsigned bl1 = *(const unsigned*)(bl0p + ks * 16 + 8);
            unsigned ch0 = *(const unsigned*)(bh0p + 512 + ks * 16);
            unsigned ch1 = *(const unsigned*)(bh0p + 512 + ks * 16 + 8);
            unsigned cl0 = *(const unsigned*)(bl0p + 512 + ks * 16);
            unsigned cl1 = *(const unsigned*)(bl0p + 512 + ks * 16 + 8);
            mma16816(dA, ah[ks][0], ah[ks][1], ah[ks][2], ah[ks][3], bh0, bh1);
            mma16816(dB, ah[ks][0], ah[ks][1], ah[ks][2], ah[ks][3], ch0, ch1);
            mma16816(dA, ah[ks][0], ah[ks][1], ah[ks][2], ah[ks][3], bl0, bl1);
            mma16816(dB, ah[ks][0], ah[ks][1], ah[ks][2], ah[ks][3], cl0, cl1);
            mma16816(dA, al[ks][0], al[ks][1], al[ks][2], al[ks][3], bh0, bh1);
            mma16816(dB, al[ks][0], al[ks][1], al[ks][2], al[ks][3], ch0, ch1);
        }
        tp_acc(jb0, dA, accS, accG, Fs, Ds, rh, le0);
        tp_acc(jb1, dB, accS, accG, Fs, Ds, rh, le0);
    }

    // scatter
    #pragma unroll
    for (int ei = 0; ei < 2; ei++) {
        int le = ei ? le1 : le0;
        int dN = Sdst[le];
        if (dN < 0) continue;
        float* mp = g_msgs + (size_t)dN * 40;
        atomicAdd(mp + c0,     PW0_8 * accS[ei][0]);
        atomicAdd(mp + c0 + 1, PW0_8 * accS[ei][1]);
        atomicAdd(mp + c0 + 8, PW0_8 * accS[ei][2]);
        atomicAdd(mp + c0 + 9, PW0_8 * accS[ei][3]);
        #pragma unroll
        for (int ci = 0; ci < 2; ci++) {
            int wv = c0 + ci;
            #pragma unroll
            for (int i = 0; i < 3; i++)
                atomicAdd(mp + 16 + wv * 3 + i, PW0_8 * accG[ei][ci][i]);
        }
    }
}

// ---------------------------------------------------------------------------
// Transpose rec_w1 [64,2560] -> TW[320,512]
// ---------------------------------------------------------------------------
__global__ void k_transpose(const float* __restrict__ rw1) {
    int idx = blockIdx.x * 256 + threadIdx.x;
    if (idx >= 320 * 512) return;
    int p = idx >> 9, r = idx & 511;
    int k = r >> 3, w = r & 7;
    g_tw[idx] = rw1[k * 2560 + p * 8 + w];
}

// ---------------------------------------------------------------------------
// Node embedding MLP + zero geo + zero msgs.
// ---------------------------------------------------------------------------
__global__ void k_embed(const float* __restrict__ x,
                        const float* __restrict__ w0,
                        const float* __restrict__ w1,
                        int N) {
    __shared__ float sh[8][64];
    int warp = threadIdx.x >> 5, lane = threadIdx.x & 31;
    int n = blockIdx.x * 8 + warp;
    if (n >= N) return;
    float xa[10];
    #pragma unroll
    for (int a = 0; a < 10; a++) xa[a] = x[n * 10 + a];
    #pragma unroll
    for (int r = 0; r < 2; r++) {
        int k = lane + r * 32;
        float s = 0.f;
        #pragma unroll
        for (int a = 0; a < 10; a++) s += xa[a] * w0[a * 64 + k];
        sh[warp][k] = silu_act(s * 0.31622776601683794f);
    }
    __syncwarp();
    if (lane < 16) {
        float s = 0.f;
        #pragma unroll
        for (int k = 0; k < 64; k++) s += sh[warp][k] * w1[k * 16 + lane];
        g_nodeA[n * 40 + lane] = s * 0.125f;
    }
    if (lane < 24) g_nodeA[n * 40 + 16 + lane] = 0.f;
    g_msgs[n * 40 + lane] = 0.f;
    if (lane < 8) g_msgs[n * 40 + 32 + lane] = 0.f;
}

// ---------------------------------------------------------------------------
// Update step. Re-zeroes g_msgs.
// ---------------------------------------------------------------------------
__global__ void k_upd(const float* __restrict__ uw0,
                      const float* __restrict__ uw1,
                      const float* __restrict__ imp,
                      int N, float degInv, int step) {
    __shared__ float cat[8][32];
    __shared__ float hh[8][64];
    int warp = threadIdx.x >> 5, lane = threadIdx.x & 31;
    int n = blockIdx.x * 8 + warp;
    if (n >= N) return;
    const float* in = step ? g_nodeB : g_nodeA;
    float* out = step ? g_nodeA : g_nodeB;
    float sc = imp[0] * degInv;
    float gscale = step ? 0.5f : 1.0f;
    if (lane < 16) {
        cat[warp][lane]      = g_msgs[n * 40 + lane] * sc;
        cat[warp][16 + lane] = in[n * 40 + lane];
    }
    __syncwarp();
    #pragma unroll
    for (int r = 0; r < 2; r++) {
        int k = lane + r * 32;
        float s = 0.f;
        #pragma unroll
        for (int a = 0; a < 32; a++) s += cat[warp][a] * uw0[a * 64 + k];
        hh[warp][k] = silu_act(s * 0.17677669529663687f);
    }
    __syncwarp();
    if (lane < 16) {
        float s = 0.f;
        #pragma unroll
        for (int k = 0; k < 64; k++) s += hh[warp][k] * uw1[k * 16 + lane];
        out[n * 40 + lane] = s * 0.125f;
    }
    if (lane < 24)
        out[n * 40 + 16 + lane] =
            (g_msgs[n * 40 + 16 + lane] * sc + in[n * 40 + 16 + lane]) * gscale;
    g_msgs[n * 40 + lane] = 0.f;
    if (lane < 8) g_msgs[n * 40 + 32 + lane] = 0.f;
}

// ---------------------------------------------------------------------------
// Inter-edge prep: rhat + dist-embed -> Hl, Hr.
// ---------------------------------------------------------------------------
__global__ void k_prep(const float* __restrict__ pos,
                       const int* __restrict__ irec, const int* __restrict__ ilig,
                       const float* __restrict__ lw0,
                       const float* __restrict__ rw0,
                       int EI) {
    int idx = blockIdx.x * 256 + threadIdx.x;
    int e = idx >> 6, k = idx & 63;
    if (e >= EI) return;
    int ir = irec[e], il = ilig[e];
    float rx = pos[il * 3]     - pos[ir * 3];
    float ry = pos[il * 3 + 1] - pos[ir * 3 + 1];
    float rz = pos[il * 3 + 2] - pos[ir * 3 + 2];
    float d = sqrtf(rx * rx + ry * ry + rz * rz);
    float inv = 1.f / d;
    if (k == 0) {
        g_rh[e * 3]     = rx * inv;
        g_rh[e * 3 + 1] = ry * inv;
        g_rh[e * 3 + 2] = rz * inv;
    }
    float s1 = 0.f, s2 = 0.f;
    #pragma unroll
    for (int a = 0; a < 20; a++) {
        float diff = d * (21.f / 5.f) - (float)(a + 1);
        float t1 = diff + 1.f, t2 = 1.f - diff;
        float v = 0.f;
        if (t1 > 0.f && t2 > 0.f) v = DEMB_C * expf(-1.f / t1 - 1.f / t2);
        s1 += v * lw0[a * 64 + k];
        s2 += v * rw0[a * 64 + k];
    }
    g_Hl[idx] = silu_act(s1 * 0.22360679774997896f);
    g_Hr[idx] = silu_act(s2 * 0.22360679774997896f);
}

// ---------------------------------------------------------------------------
// K=64 GEMM (fp32): C[M,576] = A[M,64] @ B[64,576].
// ---------------------------------------------------------------------------
__global__ void __launch_bounds__(256) k_gemm64(
        const float* __restrict__ A, const float* __restrict__ B,
        float* __restrict__ C, int M) {
    extern __shared__ float sm[];
    float* As = sm;                // [64][132]
    float* Bs = As + 64 * 132;     // [64][64]
    int t = threadIdx.x;
    int rowBase = blockIdx.y * 128;
    int nBase   = blockIdx.x * 64;
    int ar = t >> 3, ac4 = (t & 7) * 4;
    #pragma unroll
    for (int i = 0; i < 4; i++) {
        int r = rowBase + ar + 32 * i;
        #pragma unroll
        for (int h = 0; h < 2; h++) {
            int kc = ac4 + h * 32;
            float4 v = make_float4(0.f, 0.f, 0.f, 0.f);
            if (r < M) v = *(const float4*)(A + (size_t)r * 64 + kc);
            As[(kc + 0) * 132 + ar + 32 * i] = v.x;
            As[(kc + 1) * 132 + ar + 32 * i] = v.y;
            As[(kc + 2) * 132 + ar + 32 * i] = v.z;
            As[(kc + 3) * 132 + ar + 32 * i] = v.w;
        }
    }
    #pragma unroll
    for (int i = 0; i < 16; i++) {
        int idx = t + i * 256;
        int k = idx >> 6, n = idx & 63;
        Bs[idx] = B[k * 576 + nBase + n];
    }
    __syncthreads();
    int tx = t & 15, ty = t >> 4;
    float acc[8][4] = {};
    #pragma unroll 16
    for (int k = 0; k < 64; k++) {
        float4 b4 = *(float4*)&Bs[k * 64 + tx * 4];
        float4 a0 = *(float4*)&As[k * 132 + ty * 8];
        float4 a1 = *(float4*)&As[k * 132 + ty * 8 + 4];
        float av[8] = {a0.x, a0.y, a0.z, a0.w, a1.x, a1.y, a1.z, a1.w};
        #pragma unroll
        for (int i = 0; i < 8; i++) {
            acc[i][0] += av[i] * b4.x;
            acc[i][1] += av[i] * b4.y;
            acc[i][2] += av[i] * b4.z;
            acc[i][3] += av[i] * b4.w;
        }
    }
    #pragma unroll
    for (int i = 0; i < 8; i++) {
        int r = rowBase + ty * 8 + i;
        if (r < M)
            *(float4*)(C + (size_t)r * 576 + nBase + tx * 4) =
                make_float4(acc[i][0], acc[i][1], acc[i][2], acc[i][3]);
    }
}

// ---------------------------------------------------------------------------
// lig TP + Z outer-product (writes transposed Zt): 16 inter-edges per block.
// ---------------------------------------------------------------------------
__global__ void __launch_bounds__(256) k_lig_tp_z(
        const int* __restrict__ irec, const int* __restrict__ ilig,
        const float* __restrict__ Wl, int EI) {
    extern __shared__ float sm[];
    float* sh_w   = sm;                 // 16*577
    float* sh_fl  = sh_w + 9232;
    float* sh_fr  = sh_fl + 640;
    float* sh_dot = sh_fr + 640;
    float* sh_r   = sh_dot + 128;
    float* sh_le  = sh_r + 48;
    int* sh_il = (int*)(sh_le + 640);
    int* sh_ir = sh_il + 16;
    int t = threadIdx.x;
    int ebase = blockIdx.x * 16;
    int nval = min(16, EI - ebase);

    if (t < 16) {
        sh_ir[t] = (t < nval) ? irec[ebase + t] : 0;
        sh_il[t] = (t < nval) ? ilig[ebase + t] : 0;
    }
    __syncthreads();
    for (int idx = t; idx < nval * 576; idx += 256) {
        int e = idx / 576, j = idx - e * 576;
        sh_w[e * 577 + j] = Wl[(size_t)ebase * 576 + idx];
    }
    for (int idx = t; idx < 640; idx += 256) {
        int e = idx / 40, f = idx - e * 40;
        sh_fl[idx] = g_nodeA[sh_il[e] * 40 + f];
        sh_fr[idx] = g_nodeA[sh_ir[e] * 40 + f];
    }
    if (t < 48) {
        int e = t / 3;
        int ge = (e < nval) ? (ebase + e) : 0;
        sh_r[t] = g_rh[ge * 3 + (t - e * 3)];
    }
    __syncthreads();
    if (t < 128) {
        int e = t >> 3, u = t & 7;
        sh_dot[t] = sh_fl[e * 40 + 16 + u * 3] * sh_r[e * 3]
                  + sh_fl[e * 40 + 17 + u * 3] * sh_r[e * 3 + 1]
                  + sh_fl[e * 40 + 18 + u * 3] * sh_r[e * 3 + 2];
    }
    __syncthreads();
    for (int idx = t; idx < 640; idx += 256) {
        int e = idx / 40, o = idx - e * 40;
        const float* w = sh_w + e * 577;
        const float* f = sh_fl + e * 40;
        float val;
        if (o < 16) {
            float s1 = 0.f, s2 = 0.f;
            #pragma unroll
            for (int u = 0; u < 16; u++) s1 += f[u] * w[u * 16 + o];
            #pragma unroll
            for (int u = 0; u < 8; u++)  s2 += sh_dot[e * 8 + u] * w[256 + u * 16 + o];
            val = PW0_8 * (s1 + s2);
        } else {
            int v = o - 16; int wv = v / 3; int i = v - wv * 3;
            float s1 = 0.f, s2 = 0.f;
            #pragma unroll
            for (int u = 0; u < 16; u++) s1 += f[u] * w[384 + u * 8 + wv];
            #pragma unroll
            for (int u = 0; u < 8; u++)  s2 += f[16 + u * 3 + i] * w[512 + u * 8 + wv];
            val = PW1_8 * s1 * sh_r[e * 3 + i] + PW0_8 * s2;
        }
        sh_le[idx] = val;
    }
    __syncthreads();
    for (int idx = t; idx < 16 * 320; idx += 256) {
        int p = idx >> 4, e = idx & 15;
        if (e >= nval) continue;
        float z;
        if (p < 256) {
            z = sh_le[e * 40 + (p >> 4)] * sh_fr[e * 40 + (p & 15)];
        } else {
            int q = p - 256; int u = q >> 3, v = q & 7;
            z = (sh_le[e * 40 + 16 + u * 3] * sh_fr[e * 40 + 16 + v * 3]
               + sh_le[e * 40 + 17 + u * 3] * sh_fr[e * 40 + 17 + v * 3]
               + sh_le[e * 40 + 18 + u * 3] * sh_fr[e * 40 + 18 + v * 3]) * INV_SQ3;
        }
        g_Zt[(size_t)p * EIP + ebase + e] = z;
    }
}

// ---------------------------------------------------------------------------
// Rec GEMM (fp32): M[EI,512] = Z @ TW. A = Zt (K-major), cp.async 2-stage.
// ---------------------------------------------------------------------------
__global__ void __launch_bounds__(256) k_gemm_rec(
        const float* __restrict__ Zt, const float* __restrict__ TW,
        float* __restrict__ C, int M) {
    extern __shared__ float sm[];
    float* As = sm;            // [2][32][128]
    float* Bs = As + 8192;     // [2][32][64]
    unsigned int sAs = (unsigned int)__cvta_generic_to_shared(As);
    unsigned int sBs = (unsigned int)__cvta_generic_to_shared(Bs);
    int t = threadIdx.x;
    int rowBase = blockIdx.y * 128;
    int nBase   = blockIdx.x * 64;
    int tx = t & 15, ty = t >> 4;

    {
        #pragma unroll
        for (int i = 0; i < 4; i++) {
            int c = t + i * 256;
            int kr = c >> 5, c4 = (c & 31) * 4;
            cpa16(sAs + (kr * 128 + c4) * 4, Zt + (size_t)kr * EIP + rowBase + c4);
        }
        #pragma unroll
        for (int i = 0; i < 2; i++) {
            int c = t + i * 256;
            int kr = c >> 4, c4 = (c & 15) * 4;
            cpa16(sBs + (kr * 64 + c4) * 4, TW + kr * 512 + nBase + c4);
        }
        cpa_commit();
    }

    float acc[8][4] = {};
    for (int it = 0; it < 10; it++) {
        cpa_wait0();
        __syncthreads();
        if (it + 1 < 10) {
            int k0 = (it + 1) * 32;
            int b = (it + 1) & 1;
            #pragma unroll
            for (int i = 0; i < 4; i++) {
                int c = t + i * 256;
                int kr = c >> 5, c4 = (c & 31) * 4;
                cpa16(sAs + (b * 4096 + kr * 128 + c4) * 4,
                      Zt + (size_t)(k0 + kr) * EIP + rowBase + c4);
            }
            #pragma unroll
            for (int i = 0; i < 2; i++) {
                int c = t + i * 256;
                int kr = c >> 4, c4 = (c & 15) * 4;
                cpa16(sBs + (b * 2048 + kr * 64 + c4) * 4,
                      TW + (k0 + kr) * 512 + nBase + c4);
            }
            cpa_commit();
        }
        const float* Ab = As + (it & 1) * 4096;
        const float* Bb = Bs + (it & 1) * 2048;
        #pragma unroll
        for (int k = 0; k < 32; k++) {
            float4 b4 = *(const float4*)&Bb[k * 64 + tx * 4];
            float4 a0 = *(const float4*)&Ab[k * 128 + ty * 8];
            float4 a1 = *(const float4*)&Ab[k * 128 + ty * 8 + 4];
            float av[8] = {a0.x, a0.y, a0.z, a0.w, a1.x, a1.y, a1.z, a1.w};
            #pragma unroll
            for (int i = 0; i < 8; i++) {
                acc[i][0] += av[i] * b4.x;
                acc[i][1] += av[i] * b4.y;
                acc[i][2] += av[i] * b4.z;
                acc[i][3] += av[i] * b4.w;
            }
        }
        __syncthreads();
    }
    #pragma unroll
    for (int i = 0; i < 8; i++) {
        int r = rowBase + ty * 8 + i;
        if (r < M)
            *(float4*)(C + (size_t)r * 512 + nBase + tx * 4) =
                make_float4(acc[i][0], acc[i][1], acc[i][2], acc[i][3]);
    }
}

// ---------------------------------------------------------------------------
// Output: out[e,w] = PWREC_8 * sum_k Hr[e,k] * M[e,k*8+w]
// ---------------------------------------------------------------------------
__global__ void k_out(float* __restrict__ outp, int EI) {
    int idx = blockIdx.x * 256 + threadIdx.x;
    int e = idx >> 3, w = idx & 7;
    if (e >= EI) return;
    float s = 0.f;
    #pragma unroll
    for (int k = 0; k < 64; k++)
        s += g_Hr[e * 64 + k] * g_M[(size_t)e * 512 + k * 8 + w];
    outp[idx] = PWREC_8 * s;
}

// ---------------------------------------------------------------------------
extern "C" void kernel_launch(void* const* d_in, const int* in_sizes, int n_in,
                              void* d_out, int out_size) {
    const float* x     = (const float*)d_in[0];
    const float* pos   = (const float*)d_in[1];
    const int*   eidx  = (const int*)  d_in[2];
    const float* eattr = (const float*)d_in[3];
    const int*   iidx  = (const int*)  d_in[4];
    const float* emb_w0= (const float*)d_in[5];
    const float* emb_w1= (const float*)d_in[6];
    const float* imp0  = (const float*)d_in[7];
    const float* m0w0  = (const float*)d_in[8];
    const float* m0w1  = (const float*)d_in[9];
    const float* u0w0  = (const float*)d_in[10];
    const float* u0w1  = (const float*)d_in[11];
    const float* imp1  = (const float*)d_in[12];
    const float* m1w0  = (const float*)d_in[13];
    const float* m1w1  = (const float*)d_in[14];
    const float* u1w0  = (const float*)d_in[15];
    const float* u1w1  = (const float*)d_in[16];
    const float* lw0   = (const float*)d_in[17];
    const float* lw1   = (const float*)d_in[18];
    const float* rw0   = (const float*)d_in[19];
    const float* rw1   = (const float*)d_in[20];
    float* outp = (float*)d_out;

    int N  = in_sizes[0] / 10;
    int E  = in_sizes[2] / 2;
    int EI = in_sizes[4] / 2;
    float degInv = (float)(1.0 / sqrt((double)E / (double)N));

    float *pWl, *pZt, *pM, *pHl, *pTW;
    __nv_bfloat16 *pBth, *pBtl;
    cudaGetSymbolAddress((void**)&pWl, g_Wl);
    cudaGetSymbolAddress((void**)&pZt, g_Zt);
    cudaGetSymbolAddress((void**)&pM,  g_M);
    cudaGetSymbolAddress((void**)&pHl, g_Hl);
    cudaGetSymbolAddress((void**)&pTW, g_tw);
    cudaGetSymbolAddress((void**)&pBth, g_Bth);
    cudaGetSymbolAddress((void**)&pBtl, g_Btl);

    const int SM_G64 = (64 * 132 + 4096) * 4;
    const int SM_REC = (8192 + 4096) * 4;
    const int SM_LIG = (9232 + 640 + 640 + 128 + 48 + 640) * 4 + 32 * 4;
    cudaFuncSetAttribute(k_gemm64,   cudaFuncAttributeMaxDynamicSharedMemorySize, SM_G64);
    cudaFuncSetAttribute(k_gemm_rec, cudaFuncAttributeMaxDynamicSharedMemorySize, SM_REC);
    cudaFuncSetAttribute(k_lig_tp_z, cudaFuncAttributeMaxDynamicSharedMemorySize, SM_LIG);

    k_transpose<<<(320 * 512 + 255) / 256, 256>>>(rw1);
    k_prepB<<<(576 * 64 + 255) / 256, 256>>>(m0w1, 0);
    k_prepB<<<(576 * 64 + 255) / 256, 256>>>(m1w1, 1);
    k_embed<<<(N + 7) / 8, 256>>>(x, emb_w0, emb_w1, N);

    int gE = (E + 63) / 64;
    k_msg_mma<<<gE, 128>>>(pos, eidx, eidx + E, eattr, m0w0,
                           pBth, pBtl, E, 0);
    k_upd<<<(N + 7) / 8, 256>>>(u0w0, u0w1, imp0, N, degInv, 0);
    k_msg_mma<<<gE, 128>>>(pos, eidx, eidx + E, eattr, m1w0,
                           pBth + 576 * 64, pBtl + 576 * 64, E, 1);
    k_upd<<<(N + 7) / 8, 256>>>(u1w0, u1w1, imp1, N, degInv, 1);

    k_prep<<<(EI * 64 + 255) / 256, 256>>>(pos, iidx, iidx + EI, lw0, rw0, EI);
    dim3 gWl(9, (EI + 127) / 128);
    k_gemm64<<<gWl, 256, SM_G64>>>(pHl, lw1, pWl, EI);
    k_lig_tp_z<<<(EI + 15) / 16, 256, SM_LIG>>>(iidx, iidx + EI, pWl, EI);
    dim3 gM(8, (EI + 127) / 128);
    k_gemm_rec<<<gM, 256, SM_REC>>>(pZt, pTW, pM, EI);
    k_out<<<(EI * 8 + 255) / 256, 256>>>(outp, EI);
}

// round 10
// speedup vs baseline: 1.4419x; 1.1342x over previous
#include <cuda_runtime.h>
#include <cuda_bf16.h>
#include <stdint.h>
#include <math.h>

// ---------------------------------------------------------------------------
// InteractionPredictor e3nn-GNN forward.
// Msg passes: fused mma.sync bf16-split + TP + scatter (validated R9).
// Lig + rec GEMMs: generic bf16-split mma.sync GEMM (this round).
// ---------------------------------------------------------------------------
#define NMAX  16384
#define EIMAX 40960

__device__ __align__(16) float g_nodeA[NMAX * 40];
__device__ __align__(16) float g_nodeB[NMAX * 40];
__device__ __align__(16) float g_msgs [NMAX * 40];
__device__ __align__(16) float g_Wl[(size_t)EIMAX * 576]; // lig TP weights
__device__ __align__(16) float g_Hr[EIMAX * 64];
__device__ __align__(16) float g_M [(size_t)EIMAX * 512];
__device__ float g_rh[EIMAX * 3];
// bf16 hi/lo operand images
__device__ __align__(16) __nv_bfloat16 g_Bth[3][576 * 64];  // mw1(x2), lw1 transposed
__device__ __align__(16) __nv_bfloat16 g_Btl[3][576 * 64];
__device__ __align__(16) __nv_bfloat16 g_TWth[512 * 320];   // rec_w1 restructured
__device__ __align__(16) __nv_bfloat16 g_TWtl[512 * 320];
__device__ __align__(16) __nv_bfloat16 g_Hlh[EIMAX * 64];
__device__ __align__(16) __nv_bfloat16 g_Hll[EIMAX * 64];
__device__ __align__(16) __nv_bfloat16 g_Zh[(size_t)EIMAX * 320];
__device__ __align__(16) __nv_bfloat16 g_Zl[(size_t)EIMAX * 320];

#define ACT_NORM 1.6789717f
#define PW0_8    0.025515518153991443f   // sqrt(1/24)/8
#define PW1_8    0.044194173824159216f   // sqrt(1/8)/8
#define PWREC_8  0.006987712429686843f   // sqrt(1/320)/8
#define INV_SQ3  0.57735026918962576f
#define SQ3F     1.7320508075688772f
#define DEMB_C   37.716086f

__device__ __forceinline__ float silu_act(float s) {
    return s / (1.f + expf(-s)) * ACT_NORM;
}
__device__ __forceinline__ void cpa16(unsigned int dst, const void* src) {
    asm volatile("cp.async.ca.shared.global [%0], [%1], 16;" :: "r"(dst), "l"(src));
}
__device__ __forceinline__ void cpa_commit() { asm volatile("cp.async.commit_group;"); }
__device__ __forceinline__ void cpa_wait0()  { asm volatile("cp.async.wait_group 0;"); }

__device__ __forceinline__ void mma16816(float d[4],
        unsigned a0, unsigned a1, unsigned a2, unsigned a3,
        unsigned b0, unsigned b1) {
    asm volatile(
        "mma.sync.aligned.m16n8k16.row.col.f32.bf16.bf16.f32 "
        "{%0,%1,%2,%3}, {%4,%5,%6,%7}, {%8,%9}, {%0,%1,%2,%3};"
        : "+f"(d[0]), "+f"(d[1]), "+f"(d[2]), "+f"(d[3])
        : "r"(a0), "r"(a1), "r"(a2), "r"(a3), "r"(b0), "r"(b1));
}
__device__ __forceinline__ unsigned lds32(unsigned addr) {
    unsigned v;
    asm volatile("ld.shared.b32 %0, [%1];" : "=r"(v) : "r"(addr));
    return v;
}

// ---------------------------------------------------------------------------
// Generic bf16-split mma GEMM: C[M,N] = A[M,K] @ Bt[N,K]^T  (3-term hi/lo).
// A buffers must be >= roundup(M,128) rows; B rows clamped to N-1.
// BM=128, BN=128, BK=32; 256 threads (8 warps, each 32x64).
// smem per stage: Ah[128][40]b16 | Al | Bh[128][40] | Bl  = 40960 B, x2 stages.
// ---------------------------------------------------------------------------
__global__ void __launch_bounds__(256) k_mma_gemm(
        const __nv_bfloat16* __restrict__ Ah, const __nv_bfloat16* __restrict__ Al,
        const __nv_bfloat16* __restrict__ Bh, const __nv_bfloat16* __restrict__ Bl,
        float* __restrict__ C, int M, int N, int K, int ldc) {
    extern __shared__ char smx[];
    unsigned sbase = (unsigned)__cvta_generic_to_shared(smx);
    int t = threadIdx.x;
    int warp = t >> 5, lane = t & 31;
    int wm = warp >> 1, wn = warp & 1;
    int rowBase = blockIdx.y * 128;
    int nBase   = blockIdx.x * 128;
    int nIter = K >> 5;

    // prologue: stage k0=0 into buffer 0
    {
        #pragma unroll
        for (int i = 0; i < 2; i++) {
            int c = t + i * 256;
            int row = c >> 2, ch = c & 3;
            int br = min(nBase + row, N - 1);
            unsigned d = sbase + row * 80 + ch * 16;
            cpa16(d,         Ah + (size_t)(rowBase + row) * K + ch * 8);
            cpa16(d + 10240, Al + (size_t)(rowBase + row) * K + ch * 8);
            cpa16(d + 20480, Bh + (size_t)br * K + ch * 8);
            cpa16(d + 30720, Bl + (size_t)br * K + ch * 8);
        }
        cpa_commit();
    }

    float d[2][8][4];
    #pragma unroll
    for (int mi = 0; mi < 2; mi++)
        #pragma unroll
        for (int ni = 0; ni < 8; ni++)
            #pragma unroll
            for (int q = 0; q < 4; q++) d[mi][ni][q] = 0.f;

    for (int it = 0; it < nIter; it++) {
        cpa_wait0();
        __syncthreads();
        if (it + 1 < nIter) {
            int k0 = (it + 1) * 32;
            unsigned sb = sbase + ((it + 1) & 1) * 40960;
            #pragma unroll
            for (int i = 0; i < 2; i++) {
                int c = t + i * 256;
                int row = c >> 2, ch = c & 3;
                int br = min(nBase + row, N - 1);
                unsigned dd = sb + row * 80 + ch * 16;
                cpa16(dd,         Ah + (size_t)(rowBase + row) * K + k0 + ch * 8);
                cpa16(dd + 10240, Al + (size_t)(rowBase + row) * K + k0 + ch * 8);
                cpa16(dd + 20480, Bh + (size_t)br * K + k0 + ch * 8);
                cpa16(dd + 30720, Bl + (size_t)br * K + k0 + ch * 8);
            }
            cpa_commit();
        }
        unsigned ab = sbase + (it & 1) * 40960;
        unsigned bb = ab + 20480;
        #pragma unroll
        for (int ks = 0; ks < 2; ks++) {
            unsigned ka = ab + ks * 32 + (lane & 3) * 4;
            unsigned kb = bb + ks * 32 + (lane & 3) * 4;
            unsigned ah[2][4], al[2][4];
            #pragma unroll
            for (int mi = 0; mi < 2; mi++) {
                unsigned rb = (unsigned)((wm * 32 + mi * 16 + (lane >> 2)) * 80);
                ah[mi][0] = lds32(ka + rb);
                ah[mi][1] = lds32(ka + rb + 8 * 80);
                ah[mi][2] = lds32(ka + rb + 16);
                ah[mi][3] = lds32(ka + rb + 8 * 80 + 16);
                al[mi][0] = lds32(ka + rb + 10240);
                al[mi][1] = lds32(ka + rb + 8 * 80 + 10240);
                al[mi][2] = lds32(ka + rb + 16 + 10240);
                al[mi][3] = lds32(ka + rb + 8 * 80 + 16 + 10240);
            }
            #pragma unroll
            for (int ni = 0; ni < 8; ni++) {
                unsigned nb = (unsigned)((wn * 64 + ni * 8 + (lane >> 2)) * 80);
                unsigned bh0 = lds32(kb + nb);
                unsigned bh1 = lds32(kb + nb + 16);
                unsigned bl0 = lds32(kb + nb + 10240);
                unsigned bl1 = lds32(kb + nb + 16 + 10240);
                #pragma unroll
                for (int mi = 0; mi < 2; mi++) {
                    mma16816(d[mi][ni], ah[mi][0], ah[mi][1], ah[mi][2], ah[mi][3], bh0, bh1);
                    mma16816(d[mi][ni], ah[mi][0], ah[mi][1], ah[mi][2], ah[mi][3], bl0, bl1);
                    mma16816(d[mi][ni], al[mi][0], al[mi][1], al[mi][2], al[mi][3], bh0, bh1);
                }
            }
        }
        __syncthreads();
    }

    // store
    #pragma unroll
    for (int mi = 0; mi < 2; mi++) {
        #pragma unroll
        for (int ni = 0; ni < 8; ni++) {
            int r0 = rowBase + wm * 32 + mi * 16 + (lane >> 2);
            int c0 = nBase + wn * 64 + ni * 8 + (lane & 3) * 2;
            if (r0 < M && c0 < N) {
                C[(size_t)r0 * ldc + c0] = d[mi][ni][0];
                if (c0 + 1 < N) C[(size_t)r0 * ldc + c0 + 1] = d[mi][ni][1];
            }
            int r1 = r0 + 8;
            if (r1 < M && c0 < N) {
                C[(size_t)r1 * ldc + c0] = d[mi][ni][2];
                if (c0 + 1 < N) C[(size_t)r1 * ldc + c0 + 1] = d[mi][ni][3];
            }
        }
    }
}

// ---------------------------------------------------------------------------
// Pre-transpose+split mw1/lw1 -> Bt images: Bt[j*64+k] = w[k*576+j]
// ---------------------------------------------------------------------------
__global__ void k_prepB(const float* __restrict__ w, int which) {
    int idx = blockIdx.x * 256 + threadIdx.x;
    if (idx >= 576 * 64) return;
    int j = idx >> 6, k = idx & 63;
    float v = w[k * 576 + j];
    __nv_bfloat16 hi = __float2bfloat16(v);
    __nv_bfloat16 lo = __float2bfloat16(v - __bfloat162float(hi));
    g_Bth[which][idx] = hi;
    g_Btl[which][idx] = lo;
}

// ---------------------------------------------------------------------------
// rec_w1 [64,2560] -> TWt[j=kk*8+w][p] bf16 hi/lo, j<512, p<320
// ---------------------------------------------------------------------------
__global__ void k_prepTW(const float* __restrict__ rw1) {
    int idx = blockIdx.x * 256 + threadIdx.x;
    if (idx >= 512 * 320) return;
    int j = idx / 320, p = idx - j * 320;
    int kk = j >> 3, w = j & 7;
    float v = rw1[kk * 2560 + p * 8 + w];
    __nv_bfloat16 hi = __float2bfloat16(v);
    __nv_bfloat16 lo = __float2bfloat16(v - __bfloat162float(hi));
    g_TWth[idx] = hi;
    g_TWtl[idx] = lo;
}

// ---------------------------------------------------------------------------
// TP register accumulation (msg pass, validated R9).
// ---------------------------------------------------------------------------
__device__ __forceinline__ void tp_acc(int jb, const float d[4],
        float accS[2][4], float accG[2][2][3],
        const float* Fs, const float* Ds, const float rh[2][3], int le0) {
    int le1 = le0 + 8;
    if (jb < 256) {
        int u = jb >> 4, oh = (jb >> 3) & 1;
        float f0 = Fs[le0 * 41 + u];
        float f1 = Fs[le1 * 41 + u];
        accS[0][oh * 2 + 0] += f0 * d[0];
        accS[0][oh * 2 + 1] += f0 * d[1];
        accS[1][oh * 2 + 0] += f1 * d[2];
        accS[1][oh * 2 + 1] += f1 * d[3];
    } else if (jb < 384) {
        int u = (jb - 256) >> 4, oh = (jb >> 3) & 1;
        float f0 = Ds[le0 * 8 + u];
        float f1 = Ds[le1 * 8 + u];
        accS[0][oh * 2 + 0] += f0 * d[0];
        accS[0][oh * 2 + 1] += f0 * d[1];
        accS[1][oh * 2 + 0] += f1 * d[2];
        accS[1][oh * 2 + 1] += f1 * d[3];
    } else if (jb < 512) {
        int u = (jb - 384) >> 3;
        float f0 = SQ3F * Fs[le0 * 41 + u];
        float f1 = SQ3F * Fs[le1 * 41 + u];
        #pragma unroll
        for (int i = 0; i < 3; i++) {
            accG[0][0][i] += f0 * d[0] * rh[0][i];
            accG[0][1][i] += f0 * d[1] * rh[0][i];
            accG[1][0][i] += f1 * d[2] * rh[1][i];
            accG[1][1][i] += f1 * d[3] * rh[1][i];
        }
    } else {
        int u = (jb - 512) >> 3;
        #pragma unroll
        for (int i = 0; i < 3; i++) {
            float f0 = Fs[le0 * 41 + 16 + u * 3 + i];
            float f1 = Fs[le1 * 41 + 16 + u * 3 + i];
            accG[0][0][i] += f0 * d[0];
            accG[0][1][i] += f0 * d[1];
            accG[1][0][i] += f1 * d[2];
            accG[1][1][i] += f1 * d[3];
        }
    }
}

// ---------------------------------------------------------------------------
// Fused msg pass: 64 edges / block, 128 threads (validated R9).
// ---------------------------------------------------------------------------
__global__ void __launch_bounds__(128) k_msg_mma(
        const float* __restrict__ pos,
        const int* __restrict__ src, const int* __restrict__ dst,
        const float* __restrict__ eattr,
        const float* __restrict__ mw0,
        const __nv_bfloat16* __restrict__ Bth,
        const __nv_bfloat16* __restrict__ Btl,
        int E, int use_b) {
    __shared__ __nv_bfloat16 Hh[64 * 66];
    __shared__ __nv_bfloat16 Hl[64 * 66];
    __shared__ float Fs[64 * 41];
    __shared__ float Ds[64 * 8];
    __shared__ float Rs[64 * 4];
    __shared__ int   Ssrc[64];
    __shared__ int   Sdst[64];

    const float* node = use_b ? g_nodeB : g_nodeA;
    int t = threadIdx.x;
    int warp = t >> 5, lane = t & 31;
    int ebase = blockIdx.x * 64;

    if (t < 64) {
        int eid = ebase + t;
        Ssrc[t] = (eid < E) ? src[eid] : 0;
        Sdst[t] = (eid < E) ? dst[eid] : -1;
    }
    __syncthreads();

    {
        int eh = t >> 1, kb = (t & 1) * 32;
        bool hv = (ebase + eh) < E;
        float ea[5];
        #pragma unroll
        for (int a = 0; a < 5; a++)
            ea[a] = hv ? eattr[(size_t)(ebase + eh) * 5 + a] : 0.f;
        #pragma unroll
        for (int kk = 0; kk < 32; kk += 2) {
            int k = kb + kk;
            float s0 = 0.f, s1 = 0.f;
            #pragma unroll
            for (int a = 0; a < 5; a++) {
                s0 += ea[a] * __ldg(&mw0[a * 64 + k]);
                s1 += ea[a] * __ldg(&mw0[a * 64 + k + 1]);
            }
            float h0 = silu_act(s0 * 0.4472135954999579f);
            float h1 = silu_act(s1 * 0.4472135954999579f);
            __nv_bfloat16 h0h = __float2bfloat16(h0);
            __nv_bfloat16 h1h = __float2bfloat16(h1);
            __nv_bfloat16 h0l = __float2bfloat16(h0 - __bfloat162float(h0h));
            __nv_bfloat16 h1l = __float2bfloat16(h1 - __bfloat162float(h1h));
            *(__nv_bfloat162*)&Hh[eh * 66 + k] = __nv_bfloat162(h0h, h1h);
            *(__nv_bfloat162*)&Hl[eh * 66 + k] = __nv_bfloat162(h0l, h1l);
        }
    }
    for (int idx = t; idx < 2560; idx += 128) {
        int e = idx / 40, c = idx - e * 40;
        Fs[e * 41 + c] = (Sdst[e] >= 0) ? node[(size_t)Ssrc[e] * 40 + c] : 0.f;
    }
    if (t < 64) {
        float rx = 0.f, ry = 0.f, rz = 0.f;
        if (Sdst[t] >= 0) {
            const float* ps = pos + Ssrc[t] * 3;
            const float* pd = pos + Sdst[t] * 3;
            rx = pd[0] - ps[0]; ry = pd[1] - ps[1]; rz = pd[2] - ps[2];
            float inv = rsqrtf(rx * rx + ry * ry + rz * rz);
            rx *= inv; ry *= inv; rz *= inv;
        }
        Rs[t * 4] = rx; Rs[t * 4 + 1] = ry; Rs[t * 4 + 2] = rz;
    }
    __syncthreads();

    for (int idx = t; idx < 512; idx += 128) {
        int e = idx >> 3, u = idx & 7;
        Ds[idx] = Fs[e * 41 + 16 + u * 3]     * Rs[e * 4]
                + Fs[e * 41 + 17 + u * 3]     * Rs[e * 4 + 1]
                + Fs[e * 41 + 18 + u * 3]     * Rs[e * 4 + 2];
    }
    __syncthreads();

    int r0 = lane >> 2;
    int c0 = (lane & 3) * 2;
    int le0 = warp * 16 + r0;
    int le1 = le0 + 8;
    unsigned ah[4][4], al[4][4];
    #pragma unroll
    for (int ks = 0; ks < 4; ks++) {
        int kb = ks * 16 + c0;
        ah[ks][0] = *(const unsigned*)&Hh[le0 * 66 + kb];
        ah[ks][1] = *(const unsigned*)&Hh[le1 * 66 + kb];
        ah[ks][2] = *(const unsigned*)&Hh[le0 * 66 + kb + 8];
        ah[ks][3] = *(const unsigned*)&Hh[le1 * 66 + kb + 8];
        al[ks][0] = *(const unsigned*)&Hl[le0 * 66 + kb];
        al[ks][1] = *(const unsigned*)&Hl[le1 * 66 + kb];
        al[ks][2] = *(const unsigned*)&Hl[le0 * 66 + kb + 8];
        al[ks][3] = *(const unsigned*)&Hl[le1 * 66 + kb + 8];
    }
    float rh[2][3];
    #pragma unroll
    for (int i = 0; i < 3; i++) {
        rh[0][i] = Rs[le0 * 4 + i];
        rh[1][i] = Rs[le1 * 4 + i];
    }

    float accS[2][4] = {};
    float accG[2][2][3] = {};
    int n = lane >> 2;
    int kc = c0;

    #pragma unroll 1
    for (int tp = 0; tp < 36; tp++) {
        int jb0 = tp * 16, jb1 = jb0 + 8;
        const __nv_bfloat16* bh0p = Bth + (size_t)(jb0 + n) * 64 + kc;
        const __nv_bfloat16* bl0p = Btl + (size_t)(jb0 + n) * 64 + kc;
        float dA[4] = {}, dB[4] = {};
        #pragma unroll
        for (int ks = 0; ks < 4; ks++) {
            unsigned bh0 = *(const unsigned*)(bh0p + ks * 16);
            unsigned bh1 = *(const unsigned*)(bh0p + ks * 16 + 8);
            unsigned bl0 = *(const unsigned*)(bl0p + ks * 16);
            unsigned bl1 = *(const unsigned*)(bl0p + ks * 16 + 8);
            unsigned ch0 = *(const unsigned*)(bh0p + 512 + ks * 16);
            unsigned ch1 = *(const unsigned*)(bh0p + 512 + ks * 16 + 8);
            unsigned cl0 = *(const unsigned*)(bl0p + 512 + ks * 16);
            unsigned cl1 = *(const unsigned*)(bl0p + 512 + ks * 16 + 8);
            mma16816(dA, ah[ks][0], ah[ks][1], ah[ks][2], ah[ks][3], bh0, bh1);
            mma16816(dB, ah[ks][0], ah[ks][1], ah[ks][2], ah[ks][3], ch0, ch1);
            mma16816(dA, ah[ks][0], ah[ks][1], ah[ks][2], ah[ks][3], bl0, bl1);
            mma16816(dB, ah[ks][0], ah[ks][1], ah[ks][2], ah[ks][3], cl0, cl1);
            mma16816(dA, al[ks][0], al[ks][1], al[ks][2], al[ks][3], bh0, bh1);
            mma16816(dB, al[ks][0], al[ks][1], al[ks][2], al[ks][3], ch0, ch1);
        }
        tp_acc(jb0, dA, accS, accG, Fs, Ds, rh, le0);
        tp_acc(jb1, dB, accS, accG, Fs, Ds, rh, le0);
    }

    #pragma unroll
    for (int ei = 0; ei < 2; ei++) {
        int le = ei ? le1 : le0;
        int dN = Sdst[le];
        if (dN < 0) continue;
        float* mp = g_msgs + (size_t)dN * 40;
        atomicAdd(mp + c0,     PW0_8 * accS[ei][0]);
        atomicAdd(mp + c0 + 1, PW0_8 * accS[ei][1]);
        atomicAdd(mp + c0 + 8, PW0_8 * accS[ei][2]);
        atomicAdd(mp + c0 + 9, PW0_8 * accS[ei][3]);
        #pragma unroll
        for (int ci = 0; ci < 2; ci++) {
            int wv = c0 + ci;
            #pragma unroll
            for (int i = 0; i < 3; i++)
                atomicAdd(mp + 16 + wv * 3 + i, PW0_8 * accG[ei][ci][i]);
        }
    }
}

// ---------------------------------------------------------------------------
// Node embedding MLP + zero geo + zero msgs.
// ---------------------------------------------------------------------------
__global__ void k_embed(const float* __restrict__ x,
                        const float* __restrict__ w0,
                        const float* __restrict__ w1,
                        int N) {
    __shared__ float sh[8][64];
    int warp = threadIdx.x >> 5, lane = threadIdx.x & 31;
    int n = blockIdx.x * 8 + warp;
    if (n >= N) return;
    float xa[10];
    #pragma unroll
    for (int a = 0; a < 10; a++) xa[a] = x[n * 10 + a];
    #pragma unroll
    for (int r = 0; r < 2; r++) {
        int k = lane + r * 32;
        float s = 0.f;
        #pragma unroll
        for (int a = 0; a < 10; a++) s += xa[a] * w0[a * 64 + k];
        sh[warp][k] = silu_act(s * 0.31622776601683794f);
    }
    __syncwarp();
    if (lane < 16) {
        float s = 0.f;
        #pragma unroll
        for (int k = 0; k < 64; k++) s += sh[warp][k] * w1[k * 16 + lane];
        g_nodeA[n * 40 + lane] = s * 0.125f;
    }
    if (lane < 24) g_nodeA[n * 40 + 16 + lane] = 0.f;
    g_msgs[n * 40 + lane] = 0.f;
    if (lane < 8) g_msgs[n * 40 + 32 + lane] = 0.f;
}

// ---------------------------------------------------------------------------
// Update step. Re-zeroes g_msgs.
// ---------------------------------------------------------------------------
__global__ void k_upd(const float* __restrict__ uw0,
                      const float* __restrict__ uw1,
                      const float* __restrict__ imp,
                      int N, float degInv, int step) {
    __shared__ float cat[8][32];
    __shared__ float hh[8][64];
    int warp = threadIdx.x >> 5, lane = threadIdx.x & 31;
    int n = blockIdx.x * 8 + warp;
    if (n >= N) return;
    const float* in = step ? g_nodeB : g_nodeA;
    float* out = step ? g_nodeA : g_nodeB;
    float sc = imp[0] * degInv;
    float gscale = step ? 0.5f : 1.0f;
    if (lane < 16) {
        cat[warp][lane]      = g_msgs[n * 40 + lane] * sc;
        cat[warp][16 + lane] = in[n * 40 + lane];
    }
    __syncwarp();
    #pragma unroll
    for (int r = 0; r < 2; r++) {
        int k = lane + r * 32;
        float s = 0.f;
        #pragma unroll
        for (int a = 0; a < 32; a++) s += cat[warp][a] * uw0[a * 64 + k];
        hh[warp][k] = silu_act(s * 0.17677669529663687f);
    }
    __syncwarp();
    if (lane < 16) {
        float s = 0.f;
        #pragma unroll
        for (int k = 0; k < 64; k++) s += hh[warp][k] * uw1[k * 16 + lane];
        out[n * 40 + lane] = s * 0.125f;
    }
    if (lane < 24)
        out[n * 40 + 16 + lane] =
            (g_msgs[n * 40 + 16 + lane] * sc + in[n * 40 + 16 + lane]) * gscale;
    g_msgs[n * 40 + lane] = 0.f;
    if (lane < 8) g_msgs[n * 40 + 32 + lane] = 0.f;
}

// ---------------------------------------------------------------------------
// Inter-edge prep: rhat + dist-embed -> Hl (bf16 hi/lo), Hr (fp32).
// ---------------------------------------------------------------------------
__global__ void k_prep(const float* __restrict__ pos,
                       const int* __restrict__ irec, const int* __restrict__ ilig,
                       const float* __restrict__ lw0,
                       const float* __restrict__ rw0,
                       int EI) {
    int idx = blockIdx.x * 256 + threadIdx.x;
    int e = idx >> 6, k = idx & 63;
    if (e >= EI) return;
    int ir = irec[e], il = ilig[e];
    float rx = pos[il * 3]     - pos[ir * 3];
    float ry = pos[il * 3 + 1] - pos[ir * 3 + 1];
    float rz = pos[il * 3 + 2] - pos[ir * 3 + 2];
    float d = sqrtf(rx * rx + ry * ry + rz * rz);
    float inv = 1.f / d;
    if (k == 0) {
        g_rh[e * 3]     = rx * inv;
        g_rh[e * 3 + 1] = ry * inv;
        g_rh[e * 3 + 2] = rz * inv;
    }
    float s1 = 0.f, s2 = 0.f;
    #pragma unroll
    for (int a = 0; a < 20; a++) {
        float diff = d * (21.f / 5.f) - (float)(a + 1);
        float t1 = diff + 1.f, t2 = 1.f - diff;
        float v = 0.f;
        if (t1 > 0.f && t2 > 0.f) v = DEMB_C * expf(-1.f / t1 - 1.f / t2);
        s1 += v * lw0[a * 64 + k];
        s2 += v * rw0[a * 64 + k];
    }
    float hl = silu_act(s1 * 0.22360679774997896f);
    __nv_bfloat16 hh = __float2bfloat16(hl);
    g_Hlh[idx] = hh;
    g_Hll[idx] = __float2bfloat16(hl - __bfloat162float(hh));
    g_Hr[idx] = silu_act(s2 * 0.22360679774997896f);
}

// ---------------------------------------------------------------------------
// lig TP + Z (bf16 hi/lo, row-major): 16 inter-edges per block.
// ---------------------------------------------------------------------------
__global__ void __launch_bounds__(256) k_lig_tp_z(
        const int* __restrict__ irec, const int* __restrict__ ilig,
        const float* __restrict__ Wl, int EI) {
    extern __shared__ float sm[];
    float* sh_w   = sm;                 // 16*577
    float* sh_fl  = sh_w + 9232;
    float* sh_fr  = sh_fl + 640;
    float* sh_dot = sh_fr + 640;
    float* sh_r   = sh_dot + 128;
    float* sh_le  = sh_r + 48;
    int* sh_il = (int*)(sh_le + 640);
    int* sh_ir = sh_il + 16;
    int t = threadIdx.x;
    int ebase = blockIdx.x * 16;
    int nval = min(16, EI - ebase);

    if (t < 16) {
        sh_ir[t] = (t < nval) ? irec[ebase + t] : 0;
        sh_il[t] = (t < nval) ? ilig[ebase + t] : 0;
    }
    __syncthreads();
    for (int idx = t; idx < nval * 576; idx += 256) {
        int e = idx / 576, j = idx - e * 576;
        sh_w[e * 577 + j] = Wl[(size_t)ebase * 576 + idx];
    }
    for (int idx = t; idx < 640; idx += 256) {
        int e = idx / 40, f = idx - e * 40;
        sh_fl[idx] = g_nodeA[sh_il[e] * 40 + f];
        sh_fr[idx] = g_nodeA[sh_ir[e] * 40 + f];
    }
    if (t < 48) {
        int e = t / 3;
        int ge = (e < nval) ? (ebase + e) : 0;
        sh_r[t] = g_rh[ge * 3 + (t - e * 3)];
    }
    __syncthreads();
    if (t < 128) {
        int e = t >> 3, u = t & 7;
        sh_dot[t] = sh_fl[e * 40 + 16 + u * 3] * sh_r[e * 3]
                  + sh_fl[e * 40 + 17 + u * 3] * sh_r[e * 3 + 1]
                  + sh_fl[e * 40 + 18 + u * 3] * sh_r[e * 3 + 2];
    }
    __syncthreads();
    for (int idx = t; idx < 640; idx += 256) {
        int e = idx / 40, o = idx - e * 40;
        const float* w = sh_w + e * 577;
        const float* f = sh_fl + e * 40;
        float val;
        if (o < 16) {
            float s1 = 0.f, s2 = 0.f;
            #pragma unroll
            for (int u = 0; u < 16; u++) s1 += f[u] * w[u * 16 + o];
            #pragma unroll
            for (int u = 0; u < 8; u++)  s2 += sh_dot[e * 8 + u] * w[256 + u * 16 + o];
            val = PW0_8 * (s1 + s2);
        } else {
            int v = o - 16; int wv = v / 3; int i = v - wv * 3;
            float s1 = 0.f, s2 = 0.f;
            #pragma unroll
            for (int u = 0; u < 16; u++) s1 += f[u] * w[384 + u * 8 + wv];
            #pragma unroll
            for (int u = 0; u < 8; u++)  s2 += f[16 + u * 3 + i] * w[512 + u * 8 + wv];
            val = PW1_8 * s1 * sh_r[e * 3 + i] + PW0_8 * s2;
        }
        sh_le[idx] = val;
    }
    __syncthreads();
    for (int idx = t; idx < nval * 320; idx += 256) {
        int e = idx / 320, p = idx - e * 320;
        float z;
        if (p < 256) {
            z = sh_le[e * 40 + (p >> 4)] * sh_fr[e * 40 + (p & 15)];
        } else {
            int q = p - 256; int u = q >> 3, v = q & 7;
            z = (sh_le[e * 40 + 16 + u * 3] * sh_fr[e * 40 + 16 + v * 3]
               + sh_le[e * 40 + 17 + u * 3] * sh_fr[e * 40 + 17 + v * 3]
               + sh_le[e * 40 + 18 + u * 3] * sh_fr[e * 40 + 18 + v * 3]) * INV_SQ3;
        }
        __nv_bfloat16 zh = __float2bfloat16(z);
        g_Zh[(size_t)(ebase + e) * 320 + p] = zh;
        g_Zl[(size_t)(ebase + e) * 320 + p] = __float2bfloat16(z - __bfloat162float(zh));
    }
}

// ---------------------------------------------------------------------------
// Output: out[e,w] = PWREC_8 * sum_k Hr[e,k] * M[e,k*8+w]
// ---------------------------------------------------------------------------
__global__ void k_out(float* __restrict__ outp, int EI) {
    int idx = blockIdx.x * 256 + threadIdx.x;
    int e = idx >> 3, w = idx & 7;
    if (e >= EI) return;
    float s = 0.f;
    #pragma unroll
    for (int k = 0; k < 64; k++)
        s += g_Hr[e * 64 + k] * g_M[(size_t)e * 512 + k * 8 + w];
    outp[idx] = PWREC_8 * s;
}

// ---------------------------------------------------------------------------
extern "C" void kernel_launch(void* const* d_in, const int* in_sizes, int n_in,
                              void* d_out, int out_size) {
    const float* x     = (const float*)d_in[0];
    const float* pos   = (const float*)d_in[1];
    const int*   eidx  = (const int*)  d_in[2];
    const float* eattr = (const float*)d_in[3];
    const int*   iidx  = (const int*)  d_in[4];
    const float* emb_w0= (const float*)d_in[5];
    const float* emb_w1= (const float*)d_in[6];
    const float* imp0  = (const float*)d_in[7];
    const float* m0w0  = (const float*)d_in[8];
    const float* m0w1  = (const float*)d_in[9];
    const float* u0w0  = (const float*)d_in[10];
    const float* u0w1  = (const float*)d_in[11];
    const float* imp1  = (const float*)d_in[12];
    const float* m1w0  = (const float*)d_in[13];
    const float* m1w1  = (const float*)d_in[14];
    const float* u1w0  = (const float*)d_in[15];
    const float* u1w1  = (const float*)d_in[16];
    const float* lw0   = (const float*)d_in[17];
    const float* lw1   = (const float*)d_in[18];
    const float* rw0   = (const float*)d_in[19];
    const float* rw1   = (const float*)d_in[20];
    float* outp = (float*)d_out;

    int N  = in_sizes[0] / 10;
    int E  = in_sizes[2] / 2;
    int EI = in_sizes[4] / 2;
    float degInv = (float)(1.0 / sqrt((double)E / (double)N));

    float *pWl, *pM;
    __nv_bfloat16 *pBth, *pBtl, *pTWh, *pTWl, *pHlh, *pHll, *pZh, *pZl;
    cudaGetSymbolAddress((void**)&pWl,  g_Wl);
    cudaGetSymbolAddress((void**)&pM,   g_M);
    cudaGetSymbolAddress((void**)&pBth, g_Bth);
    cudaGetSymbolAddress((void**)&pBtl, g_Btl);
    cudaGetSymbolAddress((void**)&pTWh, g_TWth);
    cudaGetSymbolAddress((void**)&pTWl, g_TWtl);
    cudaGetSymbolAddress((void**)&pHlh, g_Hlh);
    cudaGetSymbolAddress((void**)&pHll, g_Hll);
    cudaGetSymbolAddress((void**)&pZh,  g_Zh);
    cudaGetSymbolAddress((void**)&pZl,  g_Zl);

    const int SM_LIG = (9232 + 640 + 640 + 128 + 48 + 640) * 4 + 32 * 4;
    const int SM_MMA = 81920;
    cudaFuncSetAttribute(k_lig_tp_z, cudaFuncAttributeMaxDynamicSharedMemorySize, SM_LIG);
    cudaFuncSetAttribute(k_mma_gemm, cudaFuncAttributeMaxDynamicSharedMemorySize, SM_MMA);

    k_prepB<<<(576 * 64 + 255) / 256, 256>>>(m0w1, 0);
    k_prepB<<<(576 * 64 + 255) / 256, 256>>>(m1w1, 1);
    k_prepB<<<(576 * 64 + 255) / 256, 256>>>(lw1, 2);
    k_prepTW<<<(512 * 320 + 255) / 256, 256>>>(rw1);
    k_embed<<<(N + 7) / 8, 256>>>(x, emb_w0, emb_w1, N);

    int gE = (E + 63) / 64;
    k_msg_mma<<<gE, 128>>>(pos, eidx, eidx + E, eattr, m0w0, pBth, pBtl, E, 0);
    k_upd<<<(N + 7) / 8, 256>>>(u0w0, u0w1, imp0, N, degInv, 0);
    k_msg_mma<<<gE, 128>>>(pos, eidx, eidx + E, eattr, m1w0,
                           pBth + 576 * 64, pBtl + 576 * 64, E, 1);
    k_upd<<<(N + 7) / 8, 256>>>(u1w0, u1w1, imp1, N, degInv, 1);

    k_prep<<<(EI * 64 + 255) / 256, 256>>>(pos, iidx, iidx + EI, lw0, rw0, EI);
    // lig weight GEMM: Wl[EI,576] = Hl[EI,64] @ lw1t[576,64]^T
    dim3 gWl(5, (EI + 127) / 128);
    k_mma_gemm<<<gWl, 256, SM_MMA>>>(pHlh, pHll, pBth + 2 * 576 * 64,
                                     pBtl + 2 * 576 * 64, pWl, EI, 576, 64, 576);
    k_lig_tp_z<<<(EI + 15) / 16, 256, SM_LIG>>>(iidx, iidx + EI, pWl, EI);
    // rec GEMM: M[EI,512] = Z[EI,320] @ TWt[512,320]^T
    dim3 gM(4, (EI + 127) / 128);
    k_mma_gemm<<<gM, 256, SM_MMA>>>(pZh, pZl, pTWh, pTWl, pM, EI, 512, 320, 512);
    k_out<<<(EI * 8 + 255) / 256, 256>>>(outp, EI);
}

// round 11
// speedup vs baseline: 1.7611x; 1.2214x over previous
#include <cuda_runtime.h>
#include <cuda_bf16.h>
#include <stdint.h>
#include <math.h>

// ---------------------------------------------------------------------------
// InteractionPredictor e3nn-GNN forward.
// Msg passes: fused mma.sync bf16-split + TP + scatter, with PACKED B
// fragments (1 LDG.128 per tile/k-step). Lig + rec GEMMs: bf16-split mma GEMM.
// ---------------------------------------------------------------------------
#define NMAX  16384
#define EIMAX 40960

__device__ __align__(16) float g_nodeA[NMAX * 40];
__device__ __align__(16) float g_nodeB[NMAX * 40];
__device__ __align__(16) float g_msgs [NMAX * 40];
__device__ __align__(16) float g_Wl[(size_t)EIMAX * 576]; // lig TP weights
__device__ __align__(16) float g_Hr[EIMAX * 64];
__device__ __align__(16) float g_M [(size_t)EIMAX * 512];
__device__ float g_rh[EIMAX * 3];
// packed msg-weight fragments: PB[pass][(jt*4+ks)*32+lane] = {bh0,bh1,bl0,bl1}
__device__ __align__(16) uint4 g_PB[2][72 * 4 * 32];
// lig lw1 transposed bf16 hi/lo image [576][64]
__device__ __align__(16) __nv_bfloat16 g_Bth[576 * 64];
__device__ __align__(16) __nv_bfloat16 g_Btl[576 * 64];
__device__ __align__(16) __nv_bfloat16 g_TWth[512 * 320];   // rec_w1 restructured
__device__ __align__(16) __nv_bfloat16 g_TWtl[512 * 320];
__device__ __align__(16) __nv_bfloat16 g_Hlh[EIMAX * 64];
__device__ __align__(16) __nv_bfloat16 g_Hll[EIMAX * 64];
__device__ __align__(16) __nv_bfloat16 g_Zh[(size_t)EIMAX * 320];
__device__ __align__(16) __nv_bfloat16 g_Zl[(size_t)EIMAX * 320];

#define ACT_NORM 1.6789717f
#define PW0_8    0.025515518153991443f   // sqrt(1/24)/8
#define PW1_8    0.044194173824159216f   // sqrt(1/8)/8
#define PWREC_8  0.006987712429686843f   // sqrt(1/320)/8
#define INV_SQ3  0.57735026918962576f
#define SQ3F     1.7320508075688772f
#define DEMB_C   37.716086f

__device__ __forceinline__ float silu_act(float s) {
    return s / (1.f + expf(-s)) * ACT_NORM;
}
__device__ __forceinline__ void cpa16(unsigned int dst, const void* src) {
    asm volatile("cp.async.ca.shared.global [%0], [%1], 16;" :: "r"(dst), "l"(src));
}
__device__ __forceinline__ void cpa_commit() { asm volatile("cp.async.commit_group;"); }
__device__ __forceinline__ void cpa_wait0()  { asm volatile("cp.async.wait_group 0;"); }

__device__ __forceinline__ void mma16816(float d[4],
        unsigned a0, unsigned a1, unsigned a2, unsigned a3,
        unsigned b0, unsigned b1) {
    asm volatile(
        "mma.sync.aligned.m16n8k16.row.col.f32.bf16.bf16.f32 "
        "{%0,%1,%2,%3}, {%4,%5,%6,%7}, {%8,%9}, {%0,%1,%2,%3};"
        : "+f"(d[0]), "+f"(d[1]), "+f"(d[2]), "+f"(d[3])
        : "r"(a0), "r"(a1), "r"(a2), "r"(a3), "r"(b0), "r"(b1));
}
__device__ __forceinline__ unsigned lds32(unsigned addr) {
    unsigned v;
    asm volatile("ld.shared.b32 %0, [%1];" : "=r"(v) : "r"(addr));
    return v;
}
__device__ __forceinline__ unsigned pack_bf16x2(float a, float b) {
    __nv_bfloat162 v(__float2bfloat16(a), __float2bfloat16(b));
    return *(unsigned*)&v;
}

// ---------------------------------------------------------------------------
// Packed msg B image: entry (jt, ks, lane) -> 16B {bh0, bh1, bl0, bl1}.
// Fragment element (j = jt*8 + (lane>>2), k = ks*16 + (lane&3)*2):
//   b0 = (w[k][j], w[k+1][j]),  b1 = (w[k+8][j], w[k+9][j])
// ---------------------------------------------------------------------------
__global__ void k_prepPB(const float* __restrict__ mw1, int which) {
    int idx = blockIdx.x * 256 + threadIdx.x;
    if (idx >= 72 * 4 * 32) return;
    int lane = idx & 31;
    int ks = (idx >> 5) & 3;
    int jt = idx >> 7;
    int j = jt * 8 + (lane >> 2);
    int k = ks * 16 + (lane & 3) * 2;
    float v00 = mw1[k * 576 + j],       v01 = mw1[(k + 1) * 576 + j];
    float v10 = mw1[(k + 8) * 576 + j], v11 = mw1[(k + 9) * 576 + j];
    float h00 = __bfloat162float(__float2bfloat16(v00));
    float h01 = __bfloat162float(__float2bfloat16(v01));
    float h10 = __bfloat162float(__float2bfloat16(v10));
    float h11 = __bfloat162float(__float2bfloat16(v11));
    uint4 o;
    o.x = pack_bf16x2(v00, v01);
    o.y = pack_bf16x2(v10, v11);
    o.z = pack_bf16x2(v00 - h00, v01 - h01);
    o.w = pack_bf16x2(v10 - h10, v11 - h11);
    g_PB[which][idx] = o;
}

// ---------------------------------------------------------------------------
// lig lw1 -> Bt images: Bt[j*64+k] = w[k*576+j] (bf16 hi/lo)
// ---------------------------------------------------------------------------
__global__ void k_prepB(const float* __restrict__ w) {
    int idx = blockIdx.x * 256 + threadIdx.x;
    if (idx >= 576 * 64) return;
    int j = idx >> 6, k = idx & 63;
    float v = w[k * 576 + j];
    __nv_bfloat16 hi = __float2bfloat16(v);
    g_Bth[idx] = hi;
    g_Btl[idx] = __float2bfloat16(v - __bfloat162float(hi));
}

// ---------------------------------------------------------------------------
// rec_w1 [64,2560] -> TWt[j=kk*8+w][p] bf16 hi/lo
// ---------------------------------------------------------------------------
__global__ void k_prepTW(const float* __restrict__ rw1) {
    int idx = blockIdx.x * 256 + threadIdx.x;
    if (idx >= 512 * 320) return;
    int j = idx / 320, p = idx - j * 320;
    int kk = j >> 3, w = j & 7;
    float v = rw1[kk * 2560 + p * 8 + w];
    __nv_bfloat16 hi = __float2bfloat16(v);
    g_TWth[idx] = hi;
    g_TWtl[idx] = __float2bfloat16(v - __bfloat162float(hi));
}

// ---------------------------------------------------------------------------
// TP register accumulation (validated R9/R10).
// ---------------------------------------------------------------------------
__device__ __forceinline__ void tp_acc(int jb, const float d[4],
        float accS[2][4], float accG[2][2][3],
        const float* Fs, const float* Ds, const float rh[2][3], int le0) {
    int le1 = le0 + 8;
    if (jb < 256) {
        int u = jb >> 4, oh = (jb >> 3) & 1;
        float f0 = Fs[le0 * 41 + u];
        float f1 = Fs[le1 * 41 + u];
        accS[0][oh * 2 + 0] += f0 * d[0];
        accS[0][oh * 2 + 1] += f0 * d[1];
        accS[1][oh * 2 + 0] += f1 * d[2];
        accS[1][oh * 2 + 1] += f1 * d[3];
    } else if (jb < 384) {
        int u = (jb - 256) >> 4, oh = (jb >> 3) & 1;
        float f0 = Ds[le0 * 8 + u];
        float f1 = Ds[le1 * 8 + u];
        accS[0][oh * 2 + 0] += f0 * d[0];
        accS[0][oh * 2 + 1] += f0 * d[1];
        accS[1][oh * 2 + 0] += f1 * d[2];
        accS[1][oh * 2 + 1] += f1 * d[3];
    } else if (jb < 512) {
        int u = (jb - 384) >> 3;
        float f0 = SQ3F * Fs[le0 * 41 + u];
        float f1 = SQ3F * Fs[le1 * 41 + u];
        #pragma unroll
        for (int i = 0; i < 3; i++) {
            accG[0][0][i] += f0 * d[0] * rh[0][i];
            accG[0][1][i] += f0 * d[1] * rh[0][i];
            accG[1][0][i] += f1 * d[2] * rh[1][i];
            accG[1][1][i] += f1 * d[3] * rh[1][i];
        }
    } else {
        int u = (jb - 512) >> 3;
        #pragma unroll
        for (int i = 0; i < 3; i++) {
            float f0 = Fs[le0 * 41 + 16 + u * 3 + i];
            float f1 = Fs[le1 * 41 + 16 + u * 3 + i];
            accG[0][0][i] += f0 * d[0];
            accG[0][1][i] += f0 * d[1];
            accG[1][0][i] += f1 * d[2];
            accG[1][1][i] += f1 * d[3];
        }
    }
}

// ---------------------------------------------------------------------------
// Fused msg pass: 64 edges / block, 128 threads; packed B fragment loads.
// ---------------------------------------------------------------------------
__global__ void __launch_bounds__(128) k_msg_mma(
        const float* __restrict__ pos,
        const int* __restrict__ src, const int* __restrict__ dst,
        const float* __restrict__ eattr,
        const float* __restrict__ mw0,
        const uint4* __restrict__ PB,
        int E, int use_b) {
    __shared__ __nv_bfloat16 Hh[64 * 66];
    __shared__ __nv_bfloat16 Hl[64 * 66];
    __shared__ float Fs[64 * 41];
    __shared__ float Ds[64 * 8];
    __shared__ float Rs[64 * 4];
    __shared__ int   Ssrc[64];
    __shared__ int   Sdst[64];

    const float* node = use_b ? g_nodeB : g_nodeA;
    int t = threadIdx.x;
    int warp = t >> 5, lane = t & 31;
    int ebase = blockIdx.x * 64;

    if (t < 64) {
        int eid = ebase + t;
        Ssrc[t] = (eid < E) ? src[eid] : 0;
        Sdst[t] = (eid < E) ? dst[eid] : -1;
    }
    __syncthreads();

    {   // hidden layer -> bf16 hi/lo A panels
        int eh = t >> 1, kb = (t & 1) * 32;
        bool hv = (ebase + eh) < E;
        float ea[5];
        #pragma unroll
        for (int a = 0; a < 5; a++)
            ea[a] = hv ? eattr[(size_t)(ebase + eh) * 5 + a] : 0.f;
        #pragma unroll
        for (int kk = 0; kk < 32; kk += 2) {
            int k = kb + kk;
            float s0 = 0.f, s1 = 0.f;
            #pragma unroll
            for (int a = 0; a < 5; a++) {
                s0 += ea[a] * __ldg(&mw0[a * 64 + k]);
                s1 += ea[a] * __ldg(&mw0[a * 64 + k + 1]);
            }
            float h0 = silu_act(s0 * 0.4472135954999579f);
            float h1 = silu_act(s1 * 0.4472135954999579f);
            __nv_bfloat16 h0h = __float2bfloat16(h0);
            __nv_bfloat16 h1h = __float2bfloat16(h1);
            __nv_bfloat16 h0l = __float2bfloat16(h0 - __bfloat162float(h0h));
            __nv_bfloat16 h1l = __float2bfloat16(h1 - __bfloat162float(h1h));
            *(__nv_bfloat162*)&Hh[eh * 66 + k] = __nv_bfloat162(h0h, h1h);
            *(__nv_bfloat162*)&Hl[eh * 66 + k] = __nv_bfloat162(h0l, h1l);
        }
    }
    for (int idx = t; idx < 2560; idx += 128) {
        int e = idx / 40, c = idx - e * 40;
        Fs[e * 41 + c] = (Sdst[e] >= 0) ? node[(size_t)Ssrc[e] * 40 + c] : 0.f;
    }
    if (t < 64) {
        float rx = 0.f, ry = 0.f, rz = 0.f;
        if (Sdst[t] >= 0) {
            const float* ps = pos + Ssrc[t] * 3;
            const float* pd = pos + Sdst[t] * 3;
            rx = pd[0] - ps[0]; ry = pd[1] - ps[1]; rz = pd[2] - ps[2];
            float inv = rsqrtf(rx * rx + ry * ry + rz * rz);
            rx *= inv; ry *= inv; rz *= inv;
        }
        Rs[t * 4] = rx; Rs[t * 4 + 1] = ry; Rs[t * 4 + 2] = rz;
    }
    __syncthreads();

    for (int idx = t; idx < 512; idx += 128) {
        int e = idx >> 3, u = idx & 7;
        Ds[idx] = Fs[e * 41 + 16 + u * 3]     * Rs[e * 4]
                + Fs[e * 41 + 17 + u * 3]     * Rs[e * 4 + 1]
                + Fs[e * 41 + 18 + u * 3]     * Rs[e * 4 + 2];
    }
    __syncthreads();

    int r0 = lane >> 2;
    int c0 = (lane & 3) * 2;
    int le0 = warp * 16 + r0;
    int le1 = le0 + 8;
    unsigned ah[4][4], al[4][4];
    #pragma unroll
    for (int ks = 0; ks < 4; ks++) {
        int kb = ks * 16 + c0;
        ah[ks][0] = *(const unsigned*)&Hh[le0 * 66 + kb];
        ah[ks][1] = *(const unsigned*)&Hh[le1 * 66 + kb];
        ah[ks][2] = *(const unsigned*)&Hh[le0 * 66 + kb + 8];
        ah[ks][3] = *(const unsigned*)&Hh[le1 * 66 + kb + 8];
        al[ks][0] = *(const unsigned*)&Hl[le0 * 66 + kb];
        al[ks][1] = *(const unsigned*)&Hl[le1 * 66 + kb];
        al[ks][2] = *(const unsigned*)&Hl[le0 * 66 + kb + 8];
        al[ks][3] = *(const unsigned*)&Hl[le1 * 66 + kb + 8];
    }
    float rh[2][3];
    #pragma unroll
    for (int i = 0; i < 3; i++) {
        rh[0][i] = Rs[le0 * 4 + i];
        rh[1][i] = Rs[le1 * 4 + i];
    }

    float accS[2][4] = {};
    float accG[2][2][3] = {};

    #pragma unroll 1
    for (int jt = 0; jt < 72; jt += 2) {
        const uint4* p0 = PB + (size_t)(jt * 4) * 32 + lane;
        const uint4* p1 = p0 + 128;             // tile jt+1
        float dA[4] = {}, dB[4] = {};
        #pragma unroll
        for (int ks = 0; ks < 4; ks++) {
            uint4 bA = p0[ks * 32];
            uint4 bB = p1[ks * 32];
            mma16816(dA, ah[ks][0], ah[ks][1], ah[ks][2], ah[ks][3], bA.x, bA.y);
            mma16816(dA, ah[ks][0], ah[ks][1], ah[ks][2], ah[ks][3], bA.z, bA.w);
            mma16816(dA, al[ks][0], al[ks][1], al[ks][2], al[ks][3], bA.x, bA.y);
            mma16816(dB, ah[ks][0], ah[ks][1], ah[ks][2], ah[ks][3], bB.x, bB.y);
            mma16816(dB, ah[ks][0], ah[ks][1], ah[ks][2], ah[ks][3], bB.z, bB.w);
            mma16816(dB, al[ks][0], al[ks][1], al[ks][2], al[ks][3], bB.x, bB.y);
        }
        tp_acc(jt * 8, dA, accS, accG, Fs, Ds, rh, le0);
        tp_acc(jt * 8 + 8, dB, accS, accG, Fs, Ds, rh, le0);
    }

    #pragma unroll
    for (int ei = 0; ei < 2; ei++) {
        int le = ei ? le1 : le0;
        int dN = Sdst[le];
        if (dN < 0) continue;
        float* mp = g_msgs + (size_t)dN * 40;
        atomicAdd(mp + c0,     PW0_8 * accS[ei][0]);
        atomicAdd(mp + c0 + 1, PW0_8 * accS[ei][1]);
        atomicAdd(mp + c0 + 8, PW0_8 * accS[ei][2]);
        atomicAdd(mp + c0 + 9, PW0_8 * accS[ei][3]);
        #pragma unroll
        for (int ci = 0; ci < 2; ci++) {
            int wv = c0 + ci;
            #pragma unroll
            for (int i = 0; i < 3; i++)
                atomicAdd(mp + 16 + wv * 3 + i, PW0_8 * accG[ei][ci][i]);
        }
    }
}

// ---------------------------------------------------------------------------
// Generic bf16-split mma GEMM (validated R10).
// ---------------------------------------------------------------------------
__global__ void __launch_bounds__(256) k_mma_gemm(
        const __nv_bfloat16* __restrict__ Ah, const __nv_bfloat16* __restrict__ Al,
        const __nv_bfloat16* __restrict__ Bh, const __nv_bfloat16* __restrict__ Bl,
        float* __restrict__ C, int M, int N, int K, int ldc) {
    extern __shared__ char smx[];
    unsigned sbase = (unsigned)__cvta_generic_to_shared(smx);
    int t = threadIdx.x;
    int warp = t >> 5, lane = t & 31;
    int wm = warp >> 1, wn = warp & 1;
    int rowBase = blockIdx.y * 128;
    int nBase   = blockIdx.x * 128;
    int nIter = K >> 5;

    {
        #pragma unroll
        for (int i = 0; i < 2; i++) {
            int c = t + i * 256;
            int row = c >> 2, ch = c & 3;
            int br = min(nBase + row, N - 1);
            unsigned d = sbase + row * 80 + ch * 16;
            cpa16(d,         Ah + (size_t)(rowBase + row) * K + ch * 8);
            cpa16(d + 10240, Al + (size_t)(rowBase + row) * K + ch * 8);
            cpa16(d + 20480, Bh + (size_t)br * K + ch * 8);
            cpa16(d + 30720, Bl + (size_t)br * K + ch * 8);
        }
        cpa_commit();
    }

    float d[2][8][4];
    #pragma unroll
    for (int mi = 0; mi < 2; mi++)
        #pragma unroll
        for (int ni = 0; ni < 8; ni++)
            #pragma unroll
            for (int q = 0; q < 4; q++) d[mi][ni][q] = 0.f;

    for (int it = 0; it < nIter; it++) {
        cpa_wait0();
        __syncthreads();
        if (it + 1 < nIter) {
            int k0 = (it + 1) * 32;
            unsigned sb = sbase + ((it + 1) & 1) * 40960;
            #pragma unroll
            for (int i = 0; i < 2; i++) {
                int c = t + i * 256;
                int row = c >> 2, ch = c & 3;
                int br = min(nBase + row, N - 1);
                unsigned dd = sb + row * 80 + ch * 16;
                cpa16(dd,         Ah + (size_t)(rowBase + row) * K + k0 + ch * 8);
                cpa16(dd + 10240, Al + (size_t)(rowBase + row) * K + k0 + ch * 8);
                cpa16(dd + 20480, Bh + (size_t)br * K + k0 + ch * 8);
                cpa16(dd + 30720, Bl + (size_t)br * K + k0 + ch * 8);
            }
            cpa_commit();
        }
        unsigned ab = sbase + (it & 1) * 40960;
        unsigned bb = ab + 20480;
        #pragma unroll
        for (int ks = 0; ks < 2; ks++) {
            unsigned ka = ab + ks * 32 + (lane & 3) * 4;
            unsigned kb = bb + ks * 32 + (lane & 3) * 4;
            unsigned ah[2][4], al[2][4];
            #pragma unroll
            for (int mi = 0; mi < 2; mi++) {
                unsigned rb = (unsigned)((wm * 32 + mi * 16 + (lane >> 2)) * 80);
                ah[mi][0] = lds32(ka + rb);
                ah[mi][1] = lds32(ka + rb + 8 * 80);
                ah[mi][2] = lds32(ka + rb + 16);
                ah[mi][3] = lds32(ka + rb + 8 * 80 + 16);
                al[mi][0] = lds32(ka + rb + 10240);
                al[mi][1] = lds32(ka + rb + 8 * 80 + 10240);
                al[mi][2] = lds32(ka + rb + 16 + 10240);
                al[mi][3] = lds32(ka + rb + 8 * 80 + 16 + 10240);
            }
            #pragma unroll
            for (int ni = 0; ni < 8; ni++) {
                unsigned nb = (unsigned)((wn * 64 + ni * 8 + (lane >> 2)) * 80);
                unsigned bh0 = lds32(kb + nb);
                unsigned bh1 = lds32(kb + nb + 16);
                unsigned bl0 = lds32(kb + nb + 10240);
                unsigned bl1 = lds32(kb + nb + 16 + 10240);
                #pragma unroll
                for (int mi = 0; mi < 2; mi++) {
                    mma16816(d[mi][ni], ah[mi][0], ah[mi][1], ah[mi][2], ah[mi][3], bh0, bh1);
                    mma16816(d[mi][ni], ah[mi][0], ah[mi][1], ah[mi][2], ah[mi][3], bl0, bl1);
                    mma16816(d[mi][ni], al[mi][0], al[mi][1], al[mi][2], al[mi][3], bh0, bh1);
                }
            }
        }
        __syncthreads();
    }

    #pragma unroll
    for (int mi = 0; mi < 2; mi++) {
        #pragma unroll
        for (int ni = 0; ni < 8; ni++) {
            int r0 = rowBase + wm * 32 + mi * 16 + (lane >> 2);
            int c0 = nBase + wn * 64 + ni * 8 + (lane & 3) * 2;
            if (r0 < M && c0 < N) {
                C[(size_t)r0 * ldc + c0] = d[mi][ni][0];
                if (c0 + 1 < N) C[(size_t)r0 * ldc + c0 + 1] = d[mi][ni][1];
            }
            int r1 = r0 + 8;
            if (r1 < M && c0 < N) {
                C[(size_t)r1 * ldc + c0] = d[mi][ni][2];
                if (c0 + 1 < N) C[(size_t)r1 * ldc + c0 + 1] = d[mi][ni][3];
            }
        }
    }
}

// ---------------------------------------------------------------------------
// Node embedding MLP + zero geo + zero msgs.
// ---------------------------------------------------------------------------
__global__ void k_embed(const float* __restrict__ x,
                        const float* __restrict__ w0,
                        const float* __restrict__ w1,
                        int N) {
    __shared__ float sh[8][64];
    int warp = threadIdx.x >> 5, lane = threadIdx.x & 31;
    int n = blockIdx.x * 8 + warp;
    if (n >= N) return;
    float xa[10];
    #pragma unroll
    for (int a = 0; a < 10; a++) xa[a] = x[n * 10 + a];
    #pragma unroll
    for (int r = 0; r < 2; r++) {
        int k = lane + r * 32;
        float s = 0.f;
        #pragma unroll
        for (int a = 0; a < 10; a++) s += xa[a] * w0[a * 64 + k];
        sh[warp][k] = silu_act(s * 0.31622776601683794f);
    }
    __syncwarp();
    if (lane < 16) {
        float s = 0.f;
        #pragma unroll
        for (int k = 0; k < 64; k++) s += sh[warp][k] * w1[k * 16 + lane];
        g_nodeA[n * 40 + lane] = s * 0.125f;
    }
    if (lane < 24) g_nodeA[n * 40 + 16 + lane] = 0.f;
    g_msgs[n * 40 + lane] = 0.f;
    if (lane < 8) g_msgs[n * 40 + 32 + lane] = 0.f;
}

// ---------------------------------------------------------------------------
// Update step. Re-zeroes g_msgs.
// ---------------------------------------------------------------------------
__global__ void k_upd(const float* __restrict__ uw0,
                      const float* __restrict__ uw1,
                      const float* __restrict__ imp,
                      int N, float degInv, int step) {
    __shared__ float cat[8][32];
    __shared__ float hh[8][64];
    int warp = threadIdx.x >> 5, lane = threadIdx.x & 31;
    int n = blockIdx.x * 8 + warp;
    if (n >= N) return;
    const float* in = step ? g_nodeB : g_nodeA;
    float* out = step ? g_nodeA : g_nodeB;
    float sc = imp[0] * degInv;
    float gscale = step ? 0.5f : 1.0f;
    if (lane < 16) {
        cat[warp][lane]      = g_msgs[n * 40 + lane] * sc;
        cat[warp][16 + lane] = in[n * 40 + lane];
    }
    __syncwarp();
    #pragma unroll
    for (int r = 0; r < 2; r++) {
        int k = lane + r * 32;
        float s = 0.f;
        #pragma unroll
        for (int a = 0; a < 32; a++) s += cat[warp][a] * uw0[a * 64 + k];
        hh[warp][k] = silu_act(s * 0.17677669529663687f);
    }
    __syncwarp();
    if (lane < 16) {
        float s = 0.f;
        #pragma unroll
        for (int k = 0; k < 64; k++) s += hh[warp][k] * uw1[k * 16 + lane];
        out[n * 40 + lane] = s * 0.125f;
    }
    if (lane < 24)
        out[n * 40 + 16 + lane] =
            (g_msgs[n * 40 + 16 + lane] * sc + in[n * 40 + 16 + lane]) * gscale;
    g_msgs[n * 40 + lane] = 0.f;
    if (lane < 8) g_msgs[n * 40 + 32 + lane] = 0.f;
}

// ---------------------------------------------------------------------------
// Inter-edge prep: rhat + dist-embed -> Hl (bf16 hi/lo), Hr (fp32).
// ---------------------------------------------------------------------------
__global__ void k_prep(const float* __restrict__ pos,
                       const int* __restrict__ irec, const int* __restrict__ ilig,
                       const float* __restrict__ lw0,
                       const float* __restrict__ rw0,
                       int EI) {
    int idx = blockIdx.x * 256 + threadIdx.x;
    int e = idx >> 6, k = idx & 63;
    if (e >= EI) return;
    int ir = irec[e], il = ilig[e];
    float rx = pos[il * 3]     - pos[ir * 3];
    float ry = pos[il * 3 + 1] - pos[ir * 3 + 1];
    float rz = pos[il * 3 + 2] - pos[ir * 3 + 2];
    float d = sqrtf(rx * rx + ry * ry + rz * rz);
    float inv = 1.f / d;
    if (k == 0) {
        g_rh[e * 3]     = rx * inv;
        g_rh[e * 3 + 1] = ry * inv;
        g_rh[e * 3 + 2] = rz * inv;
    }
    float s1 = 0.f, s2 = 0.f;
    #pragma unroll
    for (int a = 0; a < 20; a++) {
        float diff = d * (21.f / 5.f) - (float)(a + 1);
        float t1 = diff + 1.f, t2 = 1.f - diff;
        float v = 0.f;
        if (t1 > 0.f && t2 > 0.f) v = DEMB_C * expf(-1.f / t1 - 1.f / t2);
        s1 += v * lw0[a * 64 + k];
        s2 += v * rw0[a * 64 + k];
    }
    float hl = silu_act(s1 * 0.22360679774997896f);
    __nv_bfloat16 hh = __float2bfloat16(hl);
    g_Hlh[idx] = hh;
    g_Hll[idx] = __float2bfloat16(hl - __bfloat162float(hh));
    g_Hr[idx] = silu_act(s2 * 0.22360679774997896f);
}

// ---------------------------------------------------------------------------
// lig TP + Z (bf16 hi/lo, row-major): 16 inter-edges per block.
// ---------------------------------------------------------------------------
__global__ void __launch_bounds__(256) k_lig_tp_z(
        const int* __restrict__ irec, const int* __restrict__ ilig,
        const float* __restrict__ Wl, int EI) {
    extern __shared__ float sm[];
    float* sh_w   = sm;                 // 16*577
    float* sh_fl  = sh_w + 9232;
    float* sh_fr  = sh_fl + 640;
    float* sh_dot = sh_fr + 640;
    float* sh_r   = sh_dot + 128;
    float* sh_le  = sh_r + 48;
    int* sh_il = (int*)(sh_le + 640);
    int* sh_ir = sh_il + 16;
    int t = threadIdx.x;
    int ebase = blockIdx.x * 16;
    int nval = min(16, EI - ebase);

    if (t < 16) {
        sh_ir[t] = (t < nval) ? irec[ebase + t] : 0;
        sh_il[t] = (t < nval) ? ilig[ebase + t] : 0;
    }
    __syncthreads();
    for (int idx = t; idx < nval * 576; idx += 256) {
        int e = idx / 576, j = idx - e * 576;
        sh_w[e * 577 + j] = Wl[(size_t)ebase * 576 + idx];
    }
    for (int idx = t; idx < 640; idx += 256) {
        int e = idx / 40, f = idx - e * 40;
        sh_fl[idx] = g_nodeA[sh_il[e] * 40 + f];
        sh_fr[idx] = g_nodeA[sh_ir[e] * 40 + f];
    }
    if (t < 48) {
        int e = t / 3;
        int ge = (e < nval) ? (ebase + e) : 0;
        sh_r[t] = g_rh[ge * 3 + (t - e * 3)];
    }
    __syncthreads();
    if (t < 128) {
        int e = t >> 3, u = t & 7;
        sh_dot[t] = sh_fl[e * 40 + 16 + u * 3] * sh_r[e * 3]
                  + sh_fl[e * 40 + 17 + u * 3] * sh_r[e * 3 + 1]
                  + sh_fl[e * 40 + 18 + u * 3] * sh_r[e * 3 + 2];
    }
    __syncthreads();
    for (int idx = t; idx < 640; idx += 256) {
        int e = idx / 40, o = idx - e * 40;
        const float* w = sh_w + e * 577;
        const float* f = sh_fl + e * 40;
        float val;
        if (o < 16) {
            float s1 = 0.f, s2 = 0.f;
            #pragma unroll
            for (int u = 0; u < 16; u++) s1 += f[u] * w[u * 16 + o];
            #pragma unroll
            for (int u = 0; u < 8; u++)  s2 += sh_dot[e * 8 + u] * w[256 + u * 16 + o];
            val = PW0_8 * (s1 + s2);
        } else {
            int v = o - 16; int wv = v / 3; int i = v - wv * 3;
            float s1 = 0.f, s2 = 0.f;
            #pragma unroll
            for (int u = 0; u < 16; u++) s1 += f[u] * w[384 + u * 8 + wv];
            #pragma unroll
            for (int u = 0; u < 8; u++)  s2 += f[16 + u * 3 + i] * w[512 + u * 8 + wv];
            val = PW1_8 * s1 * sh_r[e * 3 + i] + PW0_8 * s2;
        }
        sh_le[idx] = val;
    }
    __syncthreads();
    for (int idx = t; idx < nval * 320; idx += 256) {
        int e = idx / 320, p = idx - e * 320;
        float z;
        if (p < 256) {
            z = sh_le[e * 40 + (p >> 4)] * sh_fr[e * 40 + (p & 15)];
        } else {
            int q = p - 256; int u = q >> 3, v = q & 7;
            z = (sh_le[e * 40 + 16 + u * 3] * sh_fr[e * 40 + 16 + v * 3]
               + sh_le[e * 40 + 17 + u * 3] * sh_fr[e * 40 + 17 + v * 3]
               + sh_le[e * 40 + 18 + u * 3] * sh_fr[e * 40 + 18 + v * 3]) * INV_SQ3;
        }
        __nv_bfloat16 zh = __float2bfloat16(z);
        g_Zh[(size_t)(ebase + e) * 320 + p] = zh;
        g_Zl[(size_t)(ebase + e) * 320 + p] = __float2bfloat16(z - __bfloat162float(zh));
    }
}

// ---------------------------------------------------------------------------
// Output: out[e,w] = PWREC_8 * sum_k Hr[e,k] * M[e,k*8+w]
// ---------------------------------------------------------------------------
__global__ void k_out(float* __restrict__ outp, int EI) {
    int idx = blockIdx.x * 256 + threadIdx.x;
    int e = idx >> 3, w = idx & 7;
    if (e >= EI) return;
    float s = 0.f;
    #pragma unroll
    for (int k = 0; k < 64; k++)
        s += g_Hr[e * 64 + k] * g_M[(size_t)e * 512 + k * 8 + w];
    outp[idx] = PWREC_8 * s;
}

// ---------------------------------------------------------------------------
extern "C" void kernel_launch(void* const* d_in, const int* in_sizes, int n_in,
                              void* d_out, int out_size) {
    const float* x     = (const float*)d_in[0];
    const float* pos   = (const float*)d_in[1];
    const int*   eidx  = (const int*)  d_in[2];
    const float* eattr = (const float*)d_in[3];
    const int*   iidx  = (const int*)  d_in[4];
    const float* emb_w0= (const float*)d_in[5];
    const float* emb_w1= (const float*)d_in[6];
    const float* imp0  = (const float*)d_in[7];
    const float* m0w0  = (const float*)d_in[8];
    const float* m0w1  = (const float*)d_in[9];
    const float* u0w0  = (const float*)d_in[10];
    const float* u0w1  = (const float*)d_in[11];
    const float* imp1  = (const float*)d_in[12];
    const float* m1w0  = (const float*)d_in[13];
    const float* m1w1  = (const float*)d_in[14];
    const float* u1w0  = (const float*)d_in[15];
    const float* u1w1  = (const float*)d_in[16];
    const float* lw0   = (const float*)d_in[17];
    const float* lw1   = (const float*)d_in[18];
    const float* rw0   = (const float*)d_in[19];
    const float* rw1   = (const float*)d_in[20];
    float* outp = (float*)d_out;

    int N  = in_sizes[0] / 10;
    int E  = in_sizes[2] / 2;
    int EI = in_sizes[4] / 2;
    float degInv = (float)(1.0 / sqrt((double)E / (double)N));

    float *pWl, *pM;
    uint4 *pPB;
    __nv_bfloat16 *pBth, *pBtl, *pTWh, *pTWl, *pHlh, *pHll, *pZh, *pZl;
    cudaGetSymbolAddress((void**)&pWl,  g_Wl);
    cudaGetSymbolAddress((void**)&pM,   g_M);
    cudaGetSymbolAddress((void**)&pPB,  g_PB);
    cudaGetSymbolAddress((void**)&pBth, g_Bth);
    cudaGetSymbolAddress((void**)&pBtl, g_Btl);
    cudaGetSymbolAddress((void**)&pTWh, g_TWth);
    cudaGetSymbolAddress((void**)&pTWl, g_TWtl);
    cudaGetSymbolAddress((void**)&pHlh, g_Hlh);
    cudaGetSymbolAddress((void**)&pHll, g_Hll);
    cudaGetSymbolAddress((void**)&pZh,  g_Zh);
    cudaGetSymbolAddress((void**)&pZl,  g_Zl);

    const int SM_LIG = (9232 + 640 + 640 + 128 + 48 + 640) * 4 + 32 * 4;
    const int SM_MMA = 81920;
    cudaFuncSetAttribute(k_lig_tp_z, cudaFuncAttributeMaxDynamicSharedMemorySize, SM_LIG);
    cudaFuncSetAttribute(k_mma_gemm, cudaFuncAttributeMaxDynamicSharedMemorySize, SM_MMA);

    k_prepPB<<<(72 * 4 * 32 + 255) / 256, 256>>>(m0w1, 0);
    k_prepPB<<<(72 * 4 * 32 + 255) / 256, 256>>>(m1w1, 1);
    k_prepB<<<(576 * 64 + 255) / 256, 256>>>(lw1);
    k_prepTW<<<(512 * 320 + 255) / 256, 256>>>(rw1);
    k_embed<<<(N + 7) / 8, 256>>>(x, emb_w0, emb_w1, N);

    int gE = (E + 63) / 64;
    k_msg_mma<<<gE, 128>>>(pos, eidx, eidx + E, eattr, m0w0, pPB, E, 0);
    k_upd<<<(N + 7) / 8, 256>>>(u0w0, u0w1, imp0, N, degInv, 0);
    k_msg_mma<<<gE, 128>>>(pos, eidx, eidx + E, eattr, m1w0,
                           pPB + 72 * 4 * 32, E, 1);
    k_upd<<<(N + 7) / 8, 256>>>(u1w0, u1w1, imp1, N, degInv, 1);

    k_prep<<<(EI * 64 + 255) / 256, 256>>>(pos, iidx, iidx + EI, lw0, rw0, EI);
    dim3 gWl(5, (EI + 127) / 128);
    k_mma_gemm<<<gWl, 256, SM_MMA>>>(pHlh, pHll, pBth, pBtl, pWl, EI, 576, 64, 576);
    k_lig_tp_z<<<(EI + 15) / 16, 256, SM_LIG>>>(iidx, iidx + EI, pWl, EI);
    dim3 gM(4, (EI + 127) / 128);
    k_mma_gemm<<<gM, 256, SM_MMA>>>(pZh, pZl, pTWh, pTWl, pM, EI, 512, 320, 512);
    k_out<<<(EI * 8 + 255) / 256, 256>>>(outp, EI);
}

// round 12
// speedup vs baseline: 2.1406x; 1.2155x over previous
#include <cuda_runtime.h>
#include <cuda_bf16.h>
#include <stdint.h>
#include <math.h>

// ---------------------------------------------------------------------------
// InteractionPredictor e3nn-GNN forward.
// Msg passes: fused mma.sync bf16-split + TP + scatter, packed B fragments,
// 2 M-tiles per warp. Lig GEMM: bf16-split mma GEMM. Rec GEMM: fused with
// the Hr output contraction (atomicAdd epilogue).
// ---------------------------------------------------------------------------
#define NMAX  16384
#define EIMAX 40960

__device__ __align__(16) float g_nodeA[NMAX * 40];
__device__ __align__(16) float g_nodeB[NMAX * 40];
__device__ __align__(16) float g_msgs [NMAX * 40];
__device__ __align__(16) float g_Wl[(size_t)EIMAX * 576]; // lig TP weights
__device__ __align__(16) float g_Hr[EIMAX * 64];
__device__ float g_rh[EIMAX * 3];
// packed msg-weight fragments: PB[pass][(jt*4+ks)*32+lane] = {bh0,bh1,bl0,bl1}
__device__ __align__(16) uint4 g_PB[2][72 * 4 * 32];
// lig lw1 transposed bf16 hi/lo image [576][64]
__device__ __align__(16) __nv_bfloat16 g_Bth[576 * 64];
__device__ __align__(16) __nv_bfloat16 g_Btl[576 * 64];
__device__ __align__(16) __nv_bfloat16 g_TWth[512 * 320];   // rec_w1 restructured
__device__ __align__(16) __nv_bfloat16 g_TWtl[512 * 320];
__device__ __align__(16) __nv_bfloat16 g_Hlh[EIMAX * 64];
__device__ __align__(16) __nv_bfloat16 g_Hll[EIMAX * 64];
__device__ __align__(16) __nv_bfloat16 g_Zh[(size_t)EIMAX * 320];
__device__ __align__(16) __nv_bfloat16 g_Zl[(size_t)EIMAX * 320];

#define ACT_NORM 1.6789717f
#define PW0_8    0.025515518153991443f   // sqrt(1/24)/8
#define PW1_8    0.044194173824159216f   // sqrt(1/8)/8
#define PWREC_8  0.006987712429686843f   // sqrt(1/320)/8
#define INV_SQ3  0.57735026918962576f
#define SQ3F     1.7320508075688772f
#define DEMB_C   37.716086f

__device__ __forceinline__ float silu_act(float s) {
    return s / (1.f + expf(-s)) * ACT_NORM;
}
__device__ __forceinline__ void cpa16(unsigned int dst, const void* src) {
    asm volatile("cp.async.ca.shared.global [%0], [%1], 16;" :: "r"(dst), "l"(src));
}
__device__ __forceinline__ void cpa_commit() { asm volatile("cp.async.commit_group;"); }
__device__ __forceinline__ void cpa_wait0()  { asm volatile("cp.async.wait_group 0;"); }

__device__ __forceinline__ void mma16816(float d[4],
        unsigned a0, unsigned a1, unsigned a2, unsigned a3,
        unsigned b0, unsigned b1) {
    asm volatile(
        "mma.sync.aligned.m16n8k16.row.col.f32.bf16.bf16.f32 "
        "{%0,%1,%2,%3}, {%4,%5,%6,%7}, {%8,%9}, {%0,%1,%2,%3};"
        : "+f"(d[0]), "+f"(d[1]), "+f"(d[2]), "+f"(d[3])
        : "r"(a0), "r"(a1), "r"(a2), "r"(a3), "r"(b0), "r"(b1));
}
__device__ __forceinline__ unsigned lds32(unsigned addr) {
    unsigned v;
    asm volatile("ld.shared.b32 %0, [%1];" : "=r"(v) : "r"(addr));
    return v;
}
__device__ __forceinline__ unsigned pack_bf16x2(float a, float b) {
    __nv_bfloat162 v(__float2bfloat16(a), __float2bfloat16(b));
    return *(unsigned*)&v;
}

// ---------------------------------------------------------------------------
// Packed msg B image (validated R11).
// ---------------------------------------------------------------------------
__global__ void k_prepPB(const float* __restrict__ mw1, int which) {
    int idx = blockIdx.x * 256 + threadIdx.x;
    if (idx >= 72 * 4 * 32) return;
    int lane = idx & 31;
    int ks = (idx >> 5) & 3;
    int jt = idx >> 7;
    int j = jt * 8 + (lane >> 2);
    int k = ks * 16 + (lane & 3) * 2;
    float v00 = mw1[k * 576 + j],       v01 = mw1[(k + 1) * 576 + j];
    float v10 = mw1[(k + 8) * 576 + j], v11 = mw1[(k + 9) * 576 + j];
    float h00 = __bfloat162float(__float2bfloat16(v00));
    float h01 = __bfloat162float(__float2bfloat16(v01));
    float h10 = __bfloat162float(__float2bfloat16(v10));
    float h11 = __bfloat162float(__float2bfloat16(v11));
    uint4 o;
    o.x = pack_bf16x2(v00, v01);
    o.y = pack_bf16x2(v10, v11);
    o.z = pack_bf16x2(v00 - h00, v01 - h01);
    o.w = pack_bf16x2(v10 - h10, v11 - h11);
    g_PB[which][idx] = o;
}

__global__ void k_prepB(const float* __restrict__ w) {
    int idx = blockIdx.x * 256 + threadIdx.x;
    if (idx >= 576 * 64) return;
    int j = idx >> 6, k = idx & 63;
    float v = w[k * 576 + j];
    __nv_bfloat16 hi = __float2bfloat16(v);
    g_Bth[idx] = hi;
    g_Btl[idx] = __float2bfloat16(v - __bfloat162float(hi));
}

__global__ void k_prepTW(const float* __restrict__ rw1) {
    int idx = blockIdx.x * 256 + threadIdx.x;
    if (idx >= 512 * 320) return;
    int j = idx / 320, p = idx - j * 320;
    int kk = j >> 3, w = j & 7;
    float v = rw1[kk * 2560 + p * 8 + w];
    __nv_bfloat16 hi = __float2bfloat16(v);
    g_TWth[idx] = hi;
    g_TWtl[idx] = __float2bfloat16(v - __bfloat162float(hi));
}

__global__ void k_zero(float* __restrict__ p, int n) {
    int idx = blockIdx.x * 256 + threadIdx.x;
    if (idx < n) p[idx] = 0.f;
}

// ---------------------------------------------------------------------------
// TP register accumulation (validated R9-R11).
// ---------------------------------------------------------------------------
__device__ __forceinline__ void tp_acc(int jb, const float d[4],
        float accS[2][4], float accG[2][2][3],
        const float* Fs, const float* Ds, const float rh[2][3], int le0) {
    int le1 = le0 + 8;
    if (jb < 256) {
        int u = jb >> 4, oh = (jb >> 3) & 1;
        float f0 = Fs[le0 * 41 + u];
        float f1 = Fs[le1 * 41 + u];
        accS[0][oh * 2 + 0] += f0 * d[0];
        accS[0][oh * 2 + 1] += f0 * d[1];
        accS[1][oh * 2 + 0] += f1 * d[2];
        accS[1][oh * 2 + 1] += f1 * d[3];
    } else if (jb < 384) {
        int u = (jb - 256) >> 4, oh = (jb >> 3) & 1;
        float f0 = Ds[le0 * 8 + u];
        float f1 = Ds[le1 * 8 + u];
        accS[0][oh * 2 + 0] += f0 * d[0];
        accS[0][oh * 2 + 1] += f0 * d[1];
        accS[1][oh * 2 + 0] += f1 * d[2];
        accS[1][oh * 2 + 1] += f1 * d[3];
    } else if (jb < 512) {
        int u = (jb - 384) >> 3;
        float f0 = SQ3F * Fs[le0 * 41 + u];
        float f1 = SQ3F * Fs[le1 * 41 + u];
        #pragma unroll
        for (int i = 0; i < 3; i++) {
            accG[0][0][i] += f0 * d[0] * rh[0][i];
            accG[0][1][i] += f0 * d[1] * rh[0][i];
            accG[1][0][i] += f1 * d[2] * rh[1][i];
            accG[1][1][i] += f1 * d[3] * rh[1][i];
        }
    } else {
        int u = (jb - 512) >> 3;
        #pragma unroll
        for (int i = 0; i < 3; i++) {
            float f0 = Fs[le0 * 41 + 16 + u * 3 + i];
            float f1 = Fs[le1 * 41 + 16 + u * 3 + i];
            accG[0][0][i] += f0 * d[0];
            accG[0][1][i] += f0 * d[1];
            accG[1][0][i] += f1 * d[2];
            accG[1][1][i] += f1 * d[3];
        }
    }
}

// ---------------------------------------------------------------------------
// Fused msg pass: 128 edges / block, 128 threads (4 warps x 32 edges,
// 2 m16 tiles per warp sharing B fragments).
// ---------------------------------------------------------------------------
__global__ void __launch_bounds__(128) k_msg_mma(
        const float* __restrict__ pos,
        const int* __restrict__ src, const int* __restrict__ dst,
        const float* __restrict__ eattr,
        const float* __restrict__ mw0,
        const uint4* __restrict__ PB,
        int E, int use_b) {
    extern __shared__ char smc[];
    __nv_bfloat16* Hh = (__nv_bfloat16*)smc;            // 128*66
    __nv_bfloat16* Hl = Hh + 128 * 66;                  // 128*66
    float* Fs = (float*)(Hl + 128 * 66);                // 128*41
    float* Ds = Fs + 128 * 41;                          // 128*8
    float* Rs = Ds + 128 * 8;                           // 128*4
    int* Ssrc = (int*)(Rs + 128 * 4);
    int* Sdst = Ssrc + 128;

    const float* node = use_b ? g_nodeB : g_nodeA;
    int t = threadIdx.x;
    int warp = t >> 5, lane = t & 31;
    int ebase = blockIdx.x * 128;

    {
        int eid = ebase + t;
        Ssrc[t] = (eid < E) ? src[eid] : 0;
        Sdst[t] = (eid < E) ? dst[eid] : -1;
    }
    __syncthreads();

    {   // hidden layer: one thread per edge, all 64 k
        bool hv = (ebase + t) < E;
        float ea[5];
        #pragma unroll
        for (int a = 0; a < 5; a++)
            ea[a] = hv ? eattr[(size_t)(ebase + t) * 5 + a] : 0.f;
        #pragma unroll
        for (int k = 0; k < 64; k += 2) {
            float s0 = 0.f, s1 = 0.f;
            #pragma unroll
            for (int a = 0; a < 5; a++) {
                s0 += ea[a] * __ldg(&mw0[a * 64 + k]);
                s1 += ea[a] * __ldg(&mw0[a * 64 + k + 1]);
            }
            float h0 = silu_act(s0 * 0.4472135954999579f);
            float h1 = silu_act(s1 * 0.4472135954999579f);
            __nv_bfloat16 h0h = __float2bfloat16(h0);
            __nv_bfloat16 h1h = __float2bfloat16(h1);
            __nv_bfloat16 h0l = __float2bfloat16(h0 - __bfloat162float(h0h));
            __nv_bfloat16 h1l = __float2bfloat16(h1 - __bfloat162float(h1h));
            *(__nv_bfloat162*)&Hh[t * 66 + k] = __nv_bfloat162(h0h, h1h);
            *(__nv_bfloat162*)&Hl[t * 66 + k] = __nv_bfloat162(h0l, h1l);
        }
    }
    for (int idx = t; idx < 5120; idx += 128) {
        int e = idx / 40, c = idx - e * 40;
        Fs[e * 41 + c] = (Sdst[e] >= 0) ? node[(size_t)Ssrc[e] * 40 + c] : 0.f;
    }
    {
        float rx = 0.f, ry = 0.f, rz = 0.f;
        if (Sdst[t] >= 0) {
            const float* ps = pos + Ssrc[t] * 3;
            const float* pd = pos + Sdst[t] * 3;
            rx = pd[0] - ps[0]; ry = pd[1] - ps[1]; rz = pd[2] - ps[2];
            float inv = rsqrtf(rx * rx + ry * ry + rz * rz);
            rx *= inv; ry *= inv; rz *= inv;
        }
        Rs[t * 4] = rx; Rs[t * 4 + 1] = ry; Rs[t * 4 + 2] = rz;
    }
    __syncthreads();

    for (int idx = t; idx < 1024; idx += 128) {
        int e = idx >> 3, u = idx & 7;
        Ds[idx] = Fs[e * 41 + 16 + u * 3]     * Rs[e * 4]
                + Fs[e * 41 + 17 + u * 3]     * Rs[e * 4 + 1]
                + Fs[e * 41 + 18 + u * 3]     * Rs[e * 4 + 2];
    }
    __syncthreads();

    int r0 = lane >> 2;
    int c0 = (lane & 3) * 2;
    unsigned ah[2][4][4], al[2][4][4];
    float rh[2][2][3];
    #pragma unroll
    for (int mt = 0; mt < 2; mt++) {
        int le0 = warp * 32 + mt * 16 + r0;
        int le1 = le0 + 8;
        #pragma unroll
        for (int ks = 0; ks < 4; ks++) {
            int kb = ks * 16 + c0;
            ah[mt][ks][0] = *(const unsigned*)&Hh[le0 * 66 + kb];
            ah[mt][ks][1] = *(const unsigned*)&Hh[le1 * 66 + kb];
            ah[mt][ks][2] = *(const unsigned*)&Hh[le0 * 66 + kb + 8];
            ah[mt][ks][3] = *(const unsigned*)&Hh[le1 * 66 + kb + 8];
            al[mt][ks][0] = *(const unsigned*)&Hl[le0 * 66 + kb];
            al[mt][ks][1] = *(const unsigned*)&Hl[le1 * 66 + kb];
            al[mt][ks][2] = *(const unsigned*)&Hl[le0 * 66 + kb + 8];
            al[mt][ks][3] = *(const unsigned*)&Hl[le1 * 66 + kb + 8];
        }
        #pragma unroll
        for (int i = 0; i < 3; i++) {
            rh[mt][0][i] = Rs[le0 * 4 + i];
            rh[mt][1][i] = Rs[le1 * 4 + i];
        }
    }

    float accS[2][2][4] = {};
    float accG[2][2][2][3] = {};

    #pragma unroll 1
    for (int jt = 0; jt < 72; jt += 2) {
        const uint4* p0 = PB + (size_t)(jt * 4) * 32 + lane;
        const uint4* p1 = p0 + 128;
        float dA[2][4] = {}, dB[2][4] = {};
        #pragma unroll
        for (int ks = 0; ks < 4; ks++) {
            uint4 bA = p0[ks * 32];
            uint4 bB = p1[ks * 32];
            #pragma unroll
            for (int mt = 0; mt < 2; mt++) {
                mma16816(dA[mt], ah[mt][ks][0], ah[mt][ks][1], ah[mt][ks][2], ah[mt][ks][3], bA.x, bA.y);
                mma16816(dA[mt], ah[mt][ks][0], ah[mt][ks][1], ah[mt][ks][2], ah[mt][ks][3], bA.z, bA.w);
                mma16816(dA[mt], al[mt][ks][0], al[mt][ks][1], al[mt][ks][2], al[mt][ks][3], bA.x, bA.y);
                mma16816(dB[mt], ah[mt][ks][0], ah[mt][ks][1], ah[mt][ks][2], ah[mt][ks][3], bB.x, bB.y);
                mma16816(dB[mt], ah[mt][ks][0], ah[mt][ks][1], ah[mt][ks][2], ah[mt][ks][3], bB.z, bB.w);
                mma16816(dB[mt], al[mt][ks][0], al[mt][ks][1], al[mt][ks][2], al[mt][ks][3], bB.x, bB.y);
            }
        }
        #pragma unroll
        for (int mt = 0; mt < 2; mt++) {
            int le0 = warp * 32 + mt * 16 + r0;
            tp_acc(jt * 8,     dA[mt], accS[mt], accG[mt], Fs, Ds, rh[mt], le0);
            tp_acc(jt * 8 + 8, dB[mt], accS[mt], accG[mt], Fs, Ds, rh[mt], le0);
        }
    }

    #pragma unroll
    for (int mt = 0; mt < 2; mt++) {
        #pragma unroll
        for (int ei = 0; ei < 2; ei++) {
            int le = warp * 32 + mt * 16 + r0 + ei * 8;
            int dN = Sdst[le];
            if (dN < 0) continue;
            float* mp = g_msgs + (size_t)dN * 40;
            atomicAdd(mp + c0,     PW0_8 * accS[mt][ei][0]);
            atomicAdd(mp + c0 + 1, PW0_8 * accS[mt][ei][1]);
            atomicAdd(mp + c0 + 8, PW0_8 * accS[mt][ei][2]);
            atomicAdd(mp + c0 + 9, PW0_8 * accS[mt][ei][3]);
            #pragma unroll
            for (int ci = 0; ci < 2; ci++) {
                int wv = c0 + ci;
                #pragma unroll
                for (int i = 0; i < 3; i++)
                    atomicAdd(mp + 16 + wv * 3 + i, PW0_8 * accG[mt][ei][ci][i]);
            }
        }
    }
}

// ---------------------------------------------------------------------------
// Generic bf16-split mma GEMM (validated R10/R11) — used for lig Wl.
// ---------------------------------------------------------------------------
__global__ void __launch_bounds__(256) k_mma_gemm(
        const __nv_bfloat16* __restrict__ Ah, const __nv_bfloat16* __restrict__ Al,
        const __nv_bfloat16* __restrict__ Bh, const __nv_bfloat16* __restrict__ Bl,
        float* __restrict__ C, int M, int N, int K, int ldc) {
    extern __shared__ char smx[];
    unsigned sbase = (unsigned)__cvta_generic_to_shared(smx);
    int t = threadIdx.x;
    int warp = t >> 5, lane = t & 31;
    int wm = warp >> 1, wn = warp & 1;
    int rowBase = blockIdx.y * 128;
    int nBase   = blockIdx.x * 128;
    int nIter = K >> 5;

    {
        #pragma unroll
        for (int i = 0; i < 2; i++) {
            int c = t + i * 256;
            int row = c >> 2, ch = c & 3;
            int br = min(nBase + row, N - 1);
            unsigned d = sbase + row * 80 + ch * 16;
            cpa16(d,         Ah + (size_t)(rowBase + row) * K + ch * 8);
            cpa16(d + 10240, Al + (size_t)(rowBase + row) * K + ch * 8);
            cpa16(d + 20480, Bh + (size_t)br * K + ch * 8);
            cpa16(d + 30720, Bl + (size_t)br * K + ch * 8);
        }
        cpa_commit();
    }

    float d[2][8][4];
    #pragma unroll
    for (int mi = 0; mi < 2; mi++)
        #pragma unroll
        for (int ni = 0; ni < 8; ni++)
            #pragma unroll
            for (int q = 0; q < 4; q++) d[mi][ni][q] = 0.f;

    for (int it = 0; it < nIter; it++) {
        cpa_wait0();
        __syncthreads();
        if (it + 1 < nIter) {
            int k0 = (it + 1) * 32;
            unsigned sb = sbase + ((it + 1) & 1) * 40960;
            #pragma unroll
            for (int i = 0; i < 2; i++) {
                int c = t + i * 256;
                int row = c >> 2, ch = c & 3;
                int br = min(nBase + row, N - 1);
                unsigned dd = sb + row * 80 + ch * 16;
                cpa16(dd,         Ah + (size_t)(rowBase + row) * K + k0 + ch * 8);
                cpa16(dd + 10240, Al + (size_t)(rowBase + row) * K + k0 + ch * 8);
                cpa16(dd + 20480, Bh + (size_t)br * K + k0 + ch * 8);
                cpa16(dd + 30720, Bl + (size_t)br * K + k0 + ch * 8);
            }
            cpa_commit();
        }
        unsigned ab = sbase + (it & 1) * 40960;
        unsigned bb = ab + 20480;
        #pragma unroll
        for (int ks = 0; ks < 2; ks++) {
            unsigned ka = ab + ks * 32 + (lane & 3) * 4;
            unsigned kb = bb + ks * 32 + (lane & 3) * 4;
            unsigned ah[2][4], al[2][4];
            #pragma unroll
            for (int mi = 0; mi < 2; mi++) {
                unsigned rb = (unsigned)((wm * 32 + mi * 16 + (lane >> 2)) * 80);
                ah[mi][0] = lds32(ka + rb);
                ah[mi][1] = lds32(ka + rb + 8 * 80);
                ah[mi][2] = lds32(ka + rb + 16);
                ah[mi][3] = lds32(ka + rb + 8 * 80 + 16);
                al[mi][0] = lds32(ka + rb + 10240);
                al[mi][1] = lds32(ka + rb + 8 * 80 + 10240);
                al[mi][2] = lds32(ka + rb + 16 + 10240);
                al[mi][3] = lds32(ka + rb + 8 * 80 + 16 + 10240);
            }
            #pragma unroll
            for (int ni = 0; ni < 8; ni++) {
                unsigned nb = (unsigned)((wn * 64 + ni * 8 + (lane >> 2)) * 80);
                unsigned bh0 = lds32(kb + nb);
                unsigned bh1 = lds32(kb + nb + 16);
                unsigned bl0 = lds32(kb + nb + 10240);
                unsigned bl1 = lds32(kb + nb + 16 + 10240);
                #pragma unroll
                for (int mi = 0; mi < 2; mi++) {
                    mma16816(d[mi][ni], ah[mi][0], ah[mi][1], ah[mi][2], ah[mi][3], bh0, bh1);
                    mma16816(d[mi][ni], ah[mi][0], ah[mi][1], ah[mi][2], ah[mi][3], bl0, bl1);
                    mma16816(d[mi][ni], al[mi][0], al[mi][1], al[mi][2], al[mi][3], bh0, bh1);
                }
            }
        }
        __syncthreads();
    }

    #pragma unroll
    for (int mi = 0; mi < 2; mi++) {
        #pragma unroll
        for (int ni = 0; ni < 8; ni++) {
            int r0 = rowBase + wm * 32 + mi * 16 + (lane >> 2);
            int c0 = nBase + wn * 64 + ni * 8 + (lane & 3) * 2;
            if (r0 < M && c0 < N) {
                C[(size_t)r0 * ldc + c0] = d[mi][ni][0];
                if (c0 + 1 < N) C[(size_t)r0 * ldc + c0 + 1] = d[mi][ni][1];
            }
            int r1 = r0 + 8;
            if (r1 < M && c0 < N) {
                C[(size_t)r1 * ldc + c0] = d[mi][ni][2];
                if (c0 + 1 < N) C[(size_t)r1 * ldc + c0 + 1] = d[mi][ni][3];
            }
        }
    }
}

// ---------------------------------------------------------------------------
// Rec GEMM fused with output contraction:
// out[e,w] += PWREC_8 * sum_k Hr[e,k] * (Z @ TWt^T)[e, k*8+w]
// N=512 fixed (grid.x = 4).
// ---------------------------------------------------------------------------
__global__ void __launch_bounds__(256) k_mma_rec(
        const __nv_bfloat16* __restrict__ Ah, const __nv_bfloat16* __restrict__ Al,
        const __nv_bfloat16* __restrict__ Bh, const __nv_bfloat16* __restrict__ Bl,
        float* __restrict__ outp, int M) {
    const int N = 512, K = 320;
    extern __shared__ char smx[];
    unsigned sbase = (unsigned)__cvta_generic_to_shared(smx);
    int t = threadIdx.x;
    int warp = t >> 5, lane = t & 31;
    int wm = warp >> 1, wn = warp & 1;
    int rowBase = blockIdx.y * 128;
    int nBase   = blockIdx.x * 128;
    int nIter = K >> 5;

    {
        #pragma unroll
        for (int i = 0; i < 2; i++) {
            int c = t + i * 256;
            int row = c >> 2, ch = c & 3;
            int br = min(nBase + row, N - 1);
            unsigned d = sbase + row * 80 + ch * 16;
            cpa16(d,         Ah + (size_t)(rowBase + row) * K + ch * 8);
            cpa16(d + 10240, Al + (size_t)(rowBase + row) * K + ch * 8);
            cpa16(d + 20480, Bh + (size_t)br * K + ch * 8);
            cpa16(d + 30720, Bl + (size_t)br * K + ch * 8);
        }
        cpa_commit();
    }

    float d[2][8][4];
    #pragma unroll
    for (int mi = 0; mi < 2; mi++)
        #pragma unroll
        for (int ni = 0; ni < 8; ni++)
            #pragma unroll
            for (int q = 0; q < 4; q++) d[mi][ni][q] = 0.f;

    for (int it = 0; it < nIter; it++) {
        cpa_wait0();
        __syncthreads();
        if (it + 1 < nIter) {
            int k0 = (it + 1) * 32;
            unsigned sb = sbase + ((it + 1) & 1) * 40960;
            #pragma unroll
            for (int i = 0; i < 2; i++) {
                int c = t + i * 256;
                int row = c >> 2, ch = c & 3;
                int br = min(nBase + row, N - 1);
                unsigned dd = sb + row * 80 + ch * 16;
                cpa16(dd,         Ah + (size_t)(rowBase + row) * K + k0 + ch * 8);
                cpa16(dd + 10240, Al + (size_t)(rowBase + row) * K + k0 + ch * 8);
                cpa16(dd + 20480, Bh + (size_t)br * K + k0 + ch * 8);
                cpa16(dd + 30720, Bl + (size_t)br * K + k0 + ch * 8);
            }
            cpa_commit();
        }
        unsigned ab = sbase + (it & 1) * 40960;
        unsigned bb = ab + 20480;
        #pragma unroll
        for (int ks = 0; ks < 2; ks++) {
            unsigned ka = ab + ks * 32 + (lane & 3) * 4;
            unsigned kb = bb + ks * 32 + (lane & 3) * 4;
            unsigned ah[2][4], al[2][4];
            #pragma unroll
            for (int mi = 0; mi < 2; mi++) {
                unsigned rb = (unsigned)((wm * 32 + mi * 16 + (lane >> 2)) * 80);
                ah[mi][0] = lds32(ka + rb);
                ah[mi][1] = lds32(ka + rb + 8 * 80);
                ah[mi][2] = lds32(ka + rb + 16);
                ah[mi][3] = lds32(ka + rb + 8 * 80 + 16);
                al[mi][0] = lds32(ka + rb + 10240);
                al[mi][1] = lds32(ka + rb + 8 * 80 + 10240);
                al[mi][2] = lds32(ka + rb + 16 + 10240);
                al[mi][3] = lds32(ka + rb + 8 * 80 + 16 + 10240);
            }
            #pragma unroll
            for (int ni = 0; ni < 8; ni++) {
                unsigned nb = (unsigned)((wn * 64 + ni * 8 + (lane >> 2)) * 80);
                unsigned bh0 = lds32(kb + nb);
                unsigned bh1 = lds32(kb + nb + 16);
                unsigned bl0 = lds32(kb + nb + 10240);
                unsigned bl1 = lds32(kb + nb + 16 + 10240);
                #pragma unroll
                for (int mi = 0; mi < 2; mi++) {
                    mma16816(d[mi][ni], ah[mi][0], ah[mi][1], ah[mi][2], ah[mi][3], bh0, bh1);
                    mma16816(d[mi][ni], ah[mi][0], ah[mi][1], ah[mi][2], ah[mi][3], bl0, bl1);
                    mma16816(d[mi][ni], al[mi][0], al[mi][1], al[mi][2], al[mi][3], bh0, bh1);
                }
            }
        }
        __syncthreads();
    }

    // fused epilogue: contract columns against Hr, atomicAdd into out
    int kb0 = (nBase >> 3) + wn * 8;
    int w0 = (lane & 3) * 2;
    #pragma unroll
    for (int mi = 0; mi < 2; mi++) {
        int r0 = rowBase + wm * 32 + mi * 16 + (lane >> 2);
        int r1 = r0 + 8;
        float a00 = 0.f, a01 = 0.f, a10 = 0.f, a11 = 0.f;
        #pragma unroll
        for (int ni = 0; ni < 8; ni++) {
            int k = kb0 + ni;
            float h0 = (r0 < M) ? g_Hr[r0 * 64 + k] : 0.f;
            float h1 = (r1 < M) ? g_Hr[r1 * 64 + k] : 0.f;
            a00 += h0 * d[mi][ni][0]; a01 += h0 * d[mi][ni][1];
            a10 += h1 * d[mi][ni][2]; a11 += h1 * d[mi][ni][3];
        }
        if (r0 < M) {
            atomicAdd(outp + r0 * 8 + w0,     PWREC_8 * a00);
            atomicAdd(outp + r0 * 8 + w0 + 1, PWREC_8 * a01);
        }
        if (r1 < M) {
            atomicAdd(outp + r1 * 8 + w0,     PWREC_8 * a10);
            atomicAdd(outp + r1 * 8 + w0 + 1, PWREC_8 * a11);
        }
    }
}

// ---------------------------------------------------------------------------
// Node embedding MLP + zero geo + zero msgs.
// ---------------------------------------------------------------------------
__global__ void k_embed(const float* __restrict__ x,
                        const float* __restrict__ w0,
                        const float* __restrict__ w1,
                        int N) {
    __shared__ float sh[8][64];
    int warp = threadIdx.x >> 5, lane = threadIdx.x & 31;
    int n = blockIdx.x * 8 + warp;
    if (n >= N) return;
    float xa[10];
    #pragma unroll
    for (int a = 0; a < 10; a++) xa[a] = x[n * 10 + a];
    #pragma unroll
    for (int r = 0; r < 2; r++) {
        int k = lane + r * 32;
        float s = 0.f;
        #pragma unroll
        for (int a = 0; a < 10; a++) s += xa[a] * w0[a * 64 + k];
        sh[warp][k] = silu_act(s * 0.31622776601683794f);
    }
    __syncwarp();
    if (lane < 16) {
        float s = 0.f;
        #pragma unroll
        for (int k = 0; k < 64; k++) s += sh[warp][k] * w1[k * 16 + lane];
        g_nodeA[n * 40 + lane] = s * 0.125f;
    }
    if (lane < 24) g_nodeA[n * 40 + 16 + lane] = 0.f;
    g_msgs[n * 40 + lane] = 0.f;
    if (lane < 8) g_msgs[n * 40 + 32 + lane] = 0.f;
}

// ---------------------------------------------------------------------------
// Update step. Re-zeroes g_msgs.
// ---------------------------------------------------------------------------
__global__ void k_upd(const float* __restrict__ uw0,
                      const float* __restrict__ uw1,
                      const float* __restrict__ imp,
                      int N, float degInv, int step) {
    __shared__ float cat[8][32];
    __shared__ float hh[8][64];
    int warp = threadIdx.x >> 5, lane = threadIdx.x & 31;
    int n = blockIdx.x * 8 + warp;
    if (n >= N) return;
    const float* in = step ? g_nodeB : g_nodeA;
    float* out = step ? g_nodeA : g_nodeB;
    float sc = imp[0] * degInv;
    float gscale = step ? 0.5f : 1.0f;
    if (lane < 16) {
        cat[warp][lane]      = g_msgs[n * 40 + lane] * sc;
        cat[warp][16 + lane] = in[n * 40 + lane];
    }
    __syncwarp();
    #pragma unroll
    for (int r = 0; r < 2; r++) {
        int k = lane + r * 32;
        float s = 0.f;
        #pragma unroll
        for (int a = 0; a < 32; a++) s += cat[warp][a] * uw0[a * 64 + k];
        hh[warp][k] = silu_act(s * 0.17677669529663687f);
    }
    __syncwarp();
    if (lane < 16) {
        float s = 0.f;
        #pragma unroll
        for (int k = 0; k < 64; k++) s += hh[warp][k] * uw1[k * 16 + lane];
        out[n * 40 + lane] = s * 0.125f;
    }
    if (lane < 24)
        out[n * 40 + 16 + lane] =
            (g_msgs[n * 40 + 16 + lane] * sc + in[n * 40 + 16 + lane]) * gscale;
    g_msgs[n * 40 + lane] = 0.f;
    if (lane < 8) g_msgs[n * 40 + 32 + lane] = 0.f;
}

// ---------------------------------------------------------------------------
// Inter-edge prep: rhat + dist-embed -> Hl (bf16 hi/lo), Hr (fp32).
// ---------------------------------------------------------------------------
__global__ void k_prep(const float* __restrict__ pos,
                       const int* __restrict__ irec, const int* __restrict__ ilig,
                       const float* __restrict__ lw0,
                       const float* __restrict__ rw0,
                       int EI) {
    int idx = blockIdx.x * 256 + threadIdx.x;
    int e = idx >> 6, k = idx & 63;
    if (e >= EI) return;
    int ir = irec[e], il = ilig[e];
    float rx = pos[il * 3]     - pos[ir * 3];
    float ry = pos[il * 3 + 1] - pos[ir * 3 + 1];
    float rz = pos[il * 3 + 2] - pos[ir * 3 + 2];
    float d = sqrtf(rx * rx + ry * ry + rz * rz);
    float inv = 1.f / d;
    if (k == 0) {
        g_rh[e * 3]     = rx * inv;
        g_rh[e * 3 + 1] = ry * inv;
        g_rh[e * 3 + 2] = rz * inv;
    }
    float s1 = 0.f, s2 = 0.f;
    #pragma unroll
    for (int a = 0; a < 20; a++) {
        float diff = d * (21.f / 5.f) - (float)(a + 1);
        float t1 = diff + 1.f, t2 = 1.f - diff;
        float v = 0.f;
        if (t1 > 0.f && t2 > 0.f) v = DEMB_C * expf(-1.f / t1 - 1.f / t2);
        s1 += v * lw0[a * 64 + k];
        s2 += v * rw0[a * 64 + k];
    }
    float hl = silu_act(s1 * 0.22360679774997896f);
    __nv_bfloat16 hh = __float2bfloat16(hl);
    g_Hlh[idx] = hh;
    g_Hll[idx] = __float2bfloat16(hl - __bfloat162float(hh));
    g_Hr[idx] = silu_act(s2 * 0.22360679774997896f);
}

// ---------------------------------------------------------------------------
// lig TP + Z (bf16 hi/lo, row-major): 16 inter-edges per block.
// ---------------------------------------------------------------------------
__global__ void __launch_bounds__(256) k_lig_tp_z(
        const int* __restrict__ irec, const int* __restrict__ ilig,
        const float* __restrict__ Wl, int EI) {
    extern __shared__ float sm[];
    float* sh_w   = sm;                 // 16*577
    float* sh_fl  = sh_w + 9232;
    float* sh_fr  = sh_fl + 640;
    float* sh_dot = sh_fr + 640;
    float* sh_r   = sh_dot + 128;
    float* sh_le  = sh_r + 48;
    int* sh_il = (int*)(sh_le + 640);
    int* sh_ir = sh_il + 16;
    int t = threadIdx.x;
    int ebase = blockIdx.x * 16;
    int nval = min(16, EI - ebase);

    if (t < 16) {
        sh_ir[t] = (t < nval) ? irec[ebase + t] : 0;
        sh_il[t] = (t < nval) ? ilig[ebase + t] : 0;
    }
    __syncthreads();
    for (int idx = t; idx < nval * 576; idx += 256) {
        int e = idx / 576, j = idx - e * 576;
        sh_w[e * 577 + j] = Wl[(size_t)ebase * 576 + idx];
    }
    for (int idx = t; idx < 640; idx += 256) {
        int e = idx / 40, f = idx - e * 40;
        sh_fl[idx] = g_nodeA[sh_il[e] * 40 + f];
        sh_fr[idx] = g_nodeA[sh_ir[e] * 40 + f];
    }
    if (t < 48) {
        int e = t / 3;
        int ge = (e < nval) ? (ebase + e) : 0;
        sh_r[t] = g_rh[ge * 3 + (t - e * 3)];
    }
    __syncthreads();
    if (t < 128) {
        int e = t >> 3, u = t & 7;
        sh_dot[t] = sh_fl[e * 40 + 16 + u * 3] * sh_r[e * 3]
                  + sh_fl[e * 40 + 17 + u * 3] * sh_r[e * 3 + 1]
                  + sh_fl[e * 40 + 18 + u * 3] * sh_r[e * 3 + 2];
    }
    __syncthreads();
    for (int idx = t; idx < 640; idx += 256) {
        int e = idx / 40, o = idx - e * 40;
        const float* w = sh_w + e * 577;
        const float* f = sh_fl + e * 40;
        float val;
        if (o < 16) {
            float s1 = 0.f, s2 = 0.f;
            #pragma unroll
            for (int u = 0; u < 16; u++) s1 += f[u] * w[u * 16 + o];
            #pragma unroll
            for (int u = 0; u < 8; u++)  s2 += sh_dot[e * 8 + u] * w[256 + u * 16 + o];
            val = PW0_8 * (s1 + s2);
        } else {
            int v = o - 16; int wv = v / 3; int i = v - wv * 3;
            float s1 = 0.f, s2 = 0.f;
            #pragma unroll
            for (int u = 0; u < 16; u++) s1 += f[u] * w[384 + u * 8 + wv];
            #pragma unroll
            for (int u = 0; u < 8; u++)  s2 += f[16 + u * 3 + i] * w[512 + u * 8 + wv];
            val = PW1_8 * s1 * sh_r[e * 3 + i] + PW0_8 * s2;
        }
        sh_le[idx] = val;
    }
    __syncthreads();
    for (int idx = t; idx < nval * 320; idx += 256) {
        int e = idx / 320, p = idx - e * 320;
        float z;
        if (p < 256) {
            z = sh_le[e * 40 + (p >> 4)] * sh_fr[e * 40 + (p & 15)];
        } else {
            int q = p - 256; int u = q >> 3, v = q & 7;
            z = (sh_le[e * 40 + 16 + u * 3] * sh_fr[e * 40 + 16 + v * 3]
               + sh_le[e * 40 + 17 + u * 3] * sh_fr[e * 40 + 17 + v * 3]
               + sh_le[e * 40 + 18 + u * 3] * sh_fr[e * 40 + 18 + v * 3]) * INV_SQ3;
        }
        __nv_bfloat16 zh = __float2bfloat16(z);
        g_Zh[(size_t)(ebase + e) * 320 + p] = zh;
        g_Zl[(size_t)(ebase + e) * 320 + p] = __float2bfloat16(z - __bfloat162float(zh));
    }
}

// ---------------------------------------------------------------------------
extern "C" void kernel_launch(void* const* d_in, const int* in_sizes, int n_in,
                              void* d_out, int out_size) {
    const float* x     = (const float*)d_in[0];
    const float* pos   = (const float*)d_in[1];
    const int*   eidx  = (const int*)  d_in[2];
    const float* eattr = (const float*)d_in[3];
    const int*   iidx  = (const int*)  d_in[4];
    const float* emb_w0= (const float*)d_in[5];
    const float* emb_w1= (const float*)d_in[6];
    const float* imp0  = (const float*)d_in[7];
    const float* m0w0  = (const float*)d_in[8];
    const float* m0w1  = (const float*)d_in[9];
    const float* u0w0  = (const float*)d_in[10];
    const float* u0w1  = (const float*)d_in[11];
    const float* imp1  = (const float*)d_in[12];
    const float* m1w0  = (const float*)d_in[13];
    const float* m1w1  = (const float*)d_in[14];
    const float* u1w0  = (const float*)d_in[15];
    const float* u1w1  = (const float*)d_in[16];
    const float* lw0   = (const float*)d_in[17];
    const float* lw1   = (const float*)d_in[18];
    const float* rw0   = (const float*)d_in[19];
    const float* rw1   = (const float*)d_in[20];
    float* outp = (float*)d_out;

    int N  = in_sizes[0] / 10;
    int E  = in_sizes[2] / 2;
    int EI = in_sizes[4] / 2;
    float degInv = (float)(1.0 / sqrt((double)E / (double)N));

    float *pWl;
    uint4 *pPB;
    __nv_bfloat16 *pBth, *pBtl, *pTWh, *pTWl, *pHlh, *pHll, *pZh, *pZl;
    cudaGetSymbolAddress((void**)&pWl,  g_Wl);
    cudaGetSymbolAddress((void**)&pPB,  g_PB);
    cudaGetSymbolAddress((void**)&pBth, g_Bth);
    cudaGetSymbolAddress((void**)&pBtl, g_Btl);
    cudaGetSymbolAddress((void**)&pTWh, g_TWth);
    cudaGetSymbolAddress((void**)&pTWl, g_TWtl);
    cudaGetSymbolAddress((void**)&pHlh, g_Hlh);
    cudaGetSymbolAddress((void**)&pHll, g_Hll);
    cudaGetSymbolAddress((void**)&pZh,  g_Zh);
    cudaGetSymbolAddress((void**)&pZl,  g_Zl);

    const int SM_LIG = (9232 + 640 + 640 + 128 + 48 + 640) * 4 + 32 * 4;
    const int SM_MMA = 81920;
    const int SM_MSG = 2 * 128 * 66 * 2 + 128 * 41 * 4 + 128 * 8 * 4
                     + 128 * 4 * 4 + 128 * 8;                // 61952
    cudaFuncSetAttribute(k_lig_tp_z, cudaFuncAttributeMaxDynamicSharedMemorySize, SM_LIG);
    cudaFuncSetAttribute(k_mma_gemm, cudaFuncAttributeMaxDynamicSharedMemorySize, SM_MMA);
    cudaFuncSetAttribute(k_mma_rec,  cudaFuncAttributeMaxDynamicSharedMemorySize, SM_MMA);
    cudaFuncSetAttribute(k_msg_mma,  cudaFuncAttributeMaxDynamicSharedMemorySize, SM_MSG);

    k_prepPB<<<(72 * 4 * 32 + 255) / 256, 256>>>(m0w1, 0);
    k_prepPB<<<(72 * 4 * 32 + 255) / 256, 256>>>(m1w1, 1);
    k_prepB<<<(576 * 64 + 255) / 256, 256>>>(lw1);
    k_prepTW<<<(512 * 320 + 255) / 256, 256>>>(rw1);
    k_zero<<<(EI * 8 + 255) / 256, 256>>>(outp, EI * 8);
    k_embed<<<(N + 7) / 8, 256>>>(x, emb_w0, emb_w1, N);

    int gE = (E + 127) / 128;
    k_msg_mma<<<gE, 128, SM_MSG>>>(pos, eidx, eidx + E, eattr, m0w0, pPB, E, 0);
    k_upd<<<(N + 7) / 8, 256>>>(u0w0, u0w1, imp0, N, degInv, 0);
    k_msg_mma<<<gE, 128, SM_MSG>>>(pos, eidx, eidx + E, eattr, m1w0,
                                   pPB + 72 * 4 * 32, E, 1);
    k_upd<<<(N + 7) / 8, 256>>>(u1w0, u1w1, imp1, N, degInv, 1);

    k_prep<<<(EI * 64 + 255) / 256, 256>>>(pos, iidx, iidx + EI, lw0, rw0, EI);
    dim3 gWl(5, (EI + 127) / 128);
    k_mma_gemm<<<gWl, 256, SM_MMA>>>(pHlh, pHll, pBth, pBtl, pWl, EI, 576, 64, 576);
    k_lig_tp_z<<<(EI + 15) / 16, 256, SM_LIG>>>(iidx, iidx + EI, pWl, EI);
    dim3 gM(4, (EI + 127) / 128);
    k_mma_rec<<<gM, 256, SM_MMA>>>(pZh, pZl, pTWh, pTWl, outp, EI);
}